// round 9
// baseline (speedup 1.0000x reference)
#include <cuda_runtime.h>
#include <cuda_fp16.h>
#include <math.h>
#include <stdint.h>

#define B_  32
#define T_  2048
#define D_  1024
#define M_  (B_ * T_)
#define NCTX 16
#define KS_  4
#define LO_SCALE 2048.0f
#define LO_INV   (1.0f / 2048.0f)

// ---------------- scratch (static device globals; no allocation) ----------------
__device__ __half g_vhi[(size_t)M_ * D_];     // 128 MB
__device__ __half g_vlo[(size_t)M_ * D_];     // 128 MB (scaled x2048)
__device__ __half g_wshi[(size_t)D_ * D_];    // Ws^T hi: [n][k]
__device__ __half g_wslo[(size_t)D_ * D_];    // Ws^T lo: [n][k] (scaled x2048)
__device__ float g_qpart[KS_ * B_ * D_];
__device__ float g_score[M_];
__device__ float g_ctxpart[NCTX * B_ * D_];

// ---------------- PTX helpers ----------------
__device__ __forceinline__ uint32_t smem_u32(const void* p) {
    uint32_t a;
    asm("{ .reg .u64 t; cvta.to.shared.u64 t, %1; cvt.u32.u64 %0, t; }" : "=r"(a) : "l"(p));
    return a;
}
__device__ __forceinline__ void cp_async16(uint32_t dst, const void* src) {
    asm volatile("cp.async.cg.shared.global [%0], [%1], 16;" :: "r"(dst), "l"(src));
}
#define CP_COMMIT asm volatile("cp.async.commit_group;" ::: "memory")
#define CP_WAIT1  asm volatile("cp.async.wait_group 1;" ::: "memory")
#define CP_WAIT0  asm volatile("cp.async.wait_group 0;" ::: "memory")

__device__ __forceinline__ void ldsm4(uint32_t* r, uint32_t addr) {
    asm volatile("ldmatrix.sync.aligned.m8n8.x4.shared.b16 {%0,%1,%2,%3}, [%4];"
        : "=r"(r[0]), "=r"(r[1]), "=r"(r[2]), "=r"(r[3]) : "r"(addr));
}
// main term: fp16 inputs, fp32 accumulate
__device__ __forceinline__ void mma_f32(float* d, const uint32_t* a, uint32_t b0, uint32_t b1) {
    asm("mma.sync.aligned.m16n8k16.row.col.f32.f16.f16.f32 "
        "{%0,%1,%2,%3}, {%4,%5,%6,%7}, {%8,%9}, {%0,%1,%2,%3};"
        : "+f"(d[0]), "+f"(d[1]), "+f"(d[2]), "+f"(d[3])
        : "r"(a[0]), "r"(a[1]), "r"(a[2]), "r"(a[3]), "r"(b0), "r"(b1));
}
// correction terms: fp16 accumulate (2x rate)
__device__ __forceinline__ void mma_f16(uint32_t* d, const uint32_t* a, uint32_t b0, uint32_t b1) {
    asm("mma.sync.aligned.m16n8k16.row.col.f16.f16.f16.f16 "
        "{%0,%1}, {%2,%3,%4,%5}, {%6,%7}, {%0,%1};"
        : "+r"(d[0]), "+r"(d[1])
        : "r"(a[0]), "r"(a[1]), "r"(a[2]), "r"(a[3]), "r"(b0), "r"(b1));
}

// ============================================================================
// conversions: f32 -> fp16 hi/lo split (lo scaled x2048)
// ============================================================================
__global__ void conv_values_kernel(const float* __restrict__ v) {
    size_t g = (size_t)blockIdx.x * 256 + threadIdx.x;   // float4 index
    float4 x = ((const float4*)v)[g];
    __half h0 = __float2half_rn(x.x), h1 = __float2half_rn(x.y);
    __half h2 = __float2half_rn(x.z), h3 = __float2half_rn(x.w);
    __half l0 = __float2half_rn((x.x - __half2float(h0)) * LO_SCALE);
    __half l1 = __float2half_rn((x.y - __half2float(h1)) * LO_SCALE);
    __half l2 = __float2half_rn((x.z - __half2float(h2)) * LO_SCALE);
    __half l3 = __float2half_rn((x.w - __half2float(h3)) * LO_SCALE);
    __half2 p;
    p.x = h0; p.y = h1; ((__half2*)g_vhi)[g * 2]     = p;
    p.x = h2; p.y = h3; ((__half2*)g_vhi)[g * 2 + 1] = p;
    p.x = l0; p.y = l1; ((__half2*)g_vlo)[g * 2]     = p;
    p.x = l2; p.y = l3; ((__half2*)g_vlo)[g * 2 + 1] = p;
}

__global__ void conv_ws_kernel(const float* __restrict__ Ws) {
    __shared__ float tile[32][33];
    const int n0 = blockIdx.x * 32, k0 = blockIdx.y * 32;
    const int tx = threadIdx.x, ty = threadIdx.y;     // (32, 8)
    #pragma unroll
    for (int i = 0; i < 32; i += 8)
        tile[ty + i][tx] = Ws[(size_t)(k0 + ty + i) * D_ + n0 + tx];
    __syncthreads();
    #pragma unroll
    for (int i = 0; i < 32; i += 8) {
        float x = tile[tx][ty + i];                   // Ws[k0+tx][n0+ty+i]
        __half h = __float2half_rn(x);
        g_wshi[(size_t)(n0 + ty + i) * D_ + k0 + tx] = h;
        g_wslo[(size_t)(n0 + ty + i) * D_ + k0 + tx] =
            __float2half_rn((x - __half2float(h)) * LO_SCALE);
    }
}

// ============================================================================
// qproj partials (k-split x4); summed during GEMM epilogue staging
// ============================================================================
__global__ void qproj_part_kernel(const float* __restrict__ query,
                                  const float* __restrict__ Wh,
                                  const float* __restrict__ bh,
                                  const float* __restrict__ bs,
                                  const float* __restrict__ bc) {
    int g  = blockIdx.x * 256 + threadIdx.x;     // 32768
    int ks = blockIdx.y;
    int u = g & (D_ - 1);
    int b = g >> 10;
    float acc = (ks == 0) ? (bh[u] + bs[u] + bc[u]) : 0.0f;
    const float* q = query + (size_t)b * D_;
    int kbeg = ks * (D_ / KS_), kend = kbeg + D_ / KS_;
    #pragma unroll 8
    for (int k = kbeg; k < kend; ++k)
        acc = fmaf(q[k], Wh[(size_t)k * D_ + u], acc);
    g_qpart[(size_t)ks * B_ * D_ + g] = acc;
}

// ============================================================================
// score GEMM: CTA = 128M x 128N subtile (loop ns=0..7 covers N=1024).
// 8 warps, warp tile 64x32. fp16 hi/lo split:
//   hh -> f32 accum (full rate), hl + lh -> shared f16 accum (2x rate).
// 3-stage cp.async pipeline, XOR-swizzled 64B-pitch smem, ldmatrix loads.
// ============================================================================
#define BUF_B 32768                 // AH 8K | AL 8K | BH 8K | BL 8K
#define O_AL  8192
#define O_BH  16384
#define O_BL  24576
#define NSTAGE 3
#define EPI_OFF (NSTAGE * BUF_B)    // 98304
#define GEMM_SMEM (EPI_OFF + (512 + 512) * 4)   // 102400

__global__ __launch_bounds__(256)
void score_gemm_kernel(const float* __restrict__ prev_cov,
                       const float* __restrict__ Wc,
                       const float* __restrict__ Vw) {
    extern __shared__ char smem[];
    const uint32_t sb = smem_u32(smem);
    float* qb_s = (float*)(smem + EPI_OFF);          // 128
    float* wc_s = qb_s + 128;
    float* vw_s = qb_s + 256;
    float* pc_s = qb_s + 384;                        // 128
    float (*Red)[4] = (float(*)[4])(qb_s + 512);     // [128][4]

    const int tid  = threadIdx.x;
    const int wid  = tid >> 5;
    const int lane = tid & 31;
    const int wm   = (wid >> 2) * 64;                // 0 / 64
    const int wn   = (wid & 3) * 32;                 // 0..96

    const int m0  = blockIdx.x * 128;
    const int b   = blockIdx.x >> 4;
    const int tt0 = (blockIdx.x & 15) * 128;

    if (tid < 128) pc_s[tid] = prev_cov[(size_t)b * T_ + tt0 + tid];

    // ---- hoisted fragment addressing (kk=16 differs by ^0x20) ----
    const int lr  = (lane & 7) + (lane & 8);
    const uint32_t k8 = lane >> 4;                   // 0/1
    uint32_t aoff[4], boff[2];
    #pragma unroll
    for (int mf = 0; mf < 4; ++mf) {
        int r = wm + mf * 16 + lr;
        aoff[mf] = (uint32_t)(r << 6) + (((k8 ^ (r >> 1)) & 3) << 4);
    }
    #pragma unroll
    for (int p = 0; p < 2; ++p) {
        int n = wn + p * 16 + lr;
        boff[p] = (uint32_t)(n << 6) + (((k8 ^ (n >> 1)) & 3) << 4) + O_BH;
    }

    float sacc[4][2];
    #pragma unroll
    for (int mf = 0; mf < 4; ++mf) { sacc[mf][0] = 0.f; sacc[mf][1] = 0.f; }

    #define ISSUE_CHUNK(c, bi, ns) do {                                        \
        uint32_t bb_ = sb + (bi) * BUF_B;                                      \
        _Pragma("unroll")                                                      \
        for (int i_ = 0; i_ < 2; ++i_) {                                       \
            int idx_ = tid + 256 * i_; int r_ = idx_ >> 2, u_ = idx_ & 3;      \
            uint32_t d_ = bb_ + (r_ << 6) + (((u_ ^ ((r_ >> 1) & 3)) & 3) << 4); \
            size_t ga_ = (size_t)(m0 + r_) * D_ + (c) * 32 + u_ * 8;           \
            size_t gb_ = (size_t)((ns) * 128 + r_) * D_ + (c) * 32 + u_ * 8;   \
            cp_async16(d_,        g_vhi + ga_);                                \
            cp_async16(d_ + O_AL, g_vlo + ga_);                                \
            cp_async16(d_ + O_BH, g_wshi + gb_);                               \
            cp_async16(d_ + O_BL, g_wslo + gb_);                               \
        }                                                                      \
        CP_COMMIT;                                                             \
    } while (0)

    for (int ns = 0; ns < 8; ++ns) {
        // stage epilogue constants for this subtile
        if (tid < 128) {
            int n = ns * 128 + tid;
            float q = g_qpart[(size_t)b * D_ + n]
                    + g_qpart[(size_t)B_ * D_ + (size_t)b * D_ + n]
                    + g_qpart[(size_t)2 * B_ * D_ + (size_t)b * D_ + n]
                    + g_qpart[(size_t)3 * B_ * D_ + (size_t)b * D_ + n];
            qb_s[tid] = q;
            wc_s[tid] = Wc[n];
            vw_s[tid] = Vw[n];
        }

        float accf[4][4][4];          // hh, f32
        uint32_t acc16[4][4][2];      // hl + lh, f16 (half2 pairs)
        #pragma unroll
        for (int i = 0; i < 4; ++i)
            #pragma unroll
            for (int j = 0; j < 4; ++j) {
                #pragma unroll
                for (int r = 0; r < 4; ++r) accf[i][j][r] = 0.0f;
                acc16[i][j][0] = 0u; acc16[i][j][1] = 0u;
            }

        ISSUE_CHUNK(0, 0, ns);
        ISSUE_CHUNK(1, 1, ns);

        for (int c = 0; c < 32; ++c) {
            if (c + 1 < 32) CP_WAIT1; else CP_WAIT0;   // chunk c resident
            __syncthreads();
            if (c + 2 < 32) ISSUE_CHUNK(c + 2, (c + 2) % NSTAGE, ns);

            const uint32_t bb = sb + (c % NSTAGE) * BUF_B;
            #pragma unroll
            for (int kk = 0; kk < 32; kk += 16) {
                const uint32_t xm = kk ? 0x20u : 0u;
                uint32_t af[4][4], bh[2][4], bl[2][4];
                // A_hi + B_hi
                #pragma unroll
                for (int mf = 0; mf < 4; ++mf) ldsm4(af[mf], (bb + aoff[mf]) ^ xm);
                #pragma unroll
                for (int p = 0; p < 2; ++p) ldsm4(bh[p], (bb + boff[p]) ^ xm);
                // hh -> f32 accum
                #pragma unroll
                for (int mf = 0; mf < 4; ++mf)
                    #pragma unroll
                    for (int p = 0; p < 2; ++p) {
                        mma_f32(accf[mf][2 * p],     af[mf], bh[p][0], bh[p][2]);
                        mma_f32(accf[mf][2 * p + 1], af[mf], bh[p][1], bh[p][3]);
                    }
                // B_lo; hl -> f16 accum (2x rate)
                #pragma unroll
                for (int p = 0; p < 2; ++p) ldsm4(bl[p], (bb + boff[p] + 8192) ^ xm);
                #pragma unroll
                for (int mf = 0; mf < 4; ++mf)
                    #pragma unroll
                    for (int p = 0; p < 2; ++p) {
                        mma_f16(acc16[mf][2 * p],     af[mf], bl[p][0], bl[p][2]);
                        mma_f16(acc16[mf][2 * p + 1], af[mf], bl[p][1], bl[p][3]);
                    }
                // A_lo (overwrite af); lh -> same f16 accum
                #pragma unroll
                for (int mf = 0; mf < 4; ++mf) ldsm4(af[mf], (bb + aoff[mf] + O_AL) ^ xm);
                #pragma unroll
                for (int mf = 0; mf < 4; ++mf)
                    #pragma unroll
                    for (int p = 0; p < 2; ++p) {
                        mma_f16(acc16[mf][2 * p],     af[mf], bh[p][0], bh[p][2]);
                        mma_f16(acc16[mf][2 * p + 1], af[mf], bh[p][1], bh[p][3]);
                    }
            }
        }

        // fused epilogue: act = hh + (hl+lh)/2048 + qb + pc*Wc; tanh * Vw
        #pragma unroll
        for (int mf = 0; mf < 4; ++mf) {
            const int rA = wm + mf * 16 + (lane >> 2);
            const float pA = pc_s[rA], pB = pc_s[rA + 8];
            float sA = 0.f, sB = 0.f;
            #pragma unroll
            for (int nf = 0; nf < 4; ++nf) {
                int c0 = wn + nf * 8 + 2 * (lane & 3);
                int c1 = c0 + 1;
                __half2 e01 = *(__half2*)&acc16[mf][nf][0];   // (row rA, c0/c1)
                __half2 e23 = *(__half2*)&acc16[mf][nf][1];   // (row rA+8, c0/c1)
                float a0 = accf[mf][nf][0] + __low2float(e01)  * LO_INV;
                float a1 = accf[mf][nf][1] + __high2float(e01) * LO_INV;
                float a2 = accf[mf][nf][2] + __low2float(e23)  * LO_INV;
                float a3 = accf[mf][nf][3] + __high2float(e23) * LO_INV;
                sA += tanhf(a0 + qb_s[c0] + pA * wc_s[c0]) * vw_s[c0];
                sA += tanhf(a1 + qb_s[c1] + pA * wc_s[c1]) * vw_s[c1];
                sB += tanhf(a2 + qb_s[c0] + pB * wc_s[c0]) * vw_s[c0];
                sB += tanhf(a3 + qb_s[c1] + pB * wc_s[c1]) * vw_s[c1];
            }
            sacc[mf][0] += sA;
            sacc[mf][1] += sB;
        }
        __syncthreads();   // before next subtile overwrites qb_s/wc_s/vw_s
    }

    // reduce over lanes (n quads) and warps (n-warps), write final scores
    #pragma unroll
    for (int mf = 0; mf < 4; ++mf) {
        float sA = sacc[mf][0], sB = sacc[mf][1];
        sA += __shfl_xor_sync(0xffffffff, sA, 1);
        sA += __shfl_xor_sync(0xffffffff, sA, 2);
        sB += __shfl_xor_sync(0xffffffff, sB, 1);
        sB += __shfl_xor_sync(0xffffffff, sB, 2);
        if ((lane & 3) == 0) {
            int rA = wm + mf * 16 + (lane >> 2);
            Red[rA][wid & 3]     = sA;
            Red[rA + 8][wid & 3] = sB;
        }
    }
    __syncthreads();
    if (tid < 128) {
        g_score[(size_t)m0 + tid] = Red[tid][0] + Red[tid][1] + Red[tid][2] + Red[tid][3];
    }
}

// ============================================================================
// softmax over T per batch; writes attention_weights + coverage
// ============================================================================
__global__ void softmax_kernel(const float* __restrict__ prev_cov,
                               const float* __restrict__ Vb,
                               float* __restrict__ out) {
    __shared__ float sc[T_];
    __shared__ float red[256];
    const int b = blockIdx.x;
    const int tid = threadIdx.x;
    const float vb = Vb[0];

    float lmax = -1e30f;
    for (int t = tid; t < T_; t += 256) {
        float s = g_score[(size_t)b * T_ + t] + vb;
        sc[t] = s;
        lmax = fmaxf(lmax, s);
    }
    red[tid] = lmax;
    __syncthreads();
    for (int st = 128; st > 0; st >>= 1) {
        if (tid < st) red[tid] = fmaxf(red[tid], red[tid + st]);
        __syncthreads();
    }
    const float mx = red[0];
    __syncthreads();

    float lsum = 0.0f;
    for (int t = tid; t < T_; t += 256) {
        float e = expf(sc[t] - mx);
        sc[t] = e;
        lsum += e;
    }
    red[tid] = lsum;
    __syncthreads();
    for (int st = 128; st > 0; st >>= 1) {
        if (tid < st) red[tid] += red[tid + st];
        __syncthreads();
    }
    const float inv = 1.0f / red[0];

    float* aw_out  = out + B_ * D_;
    float* cov_out = out + B_ * D_ + B_ * T_;
    const float* pc = prev_cov + (size_t)b * T_;
    for (int t = tid; t < T_; t += 256) {
        float a = sc[t] * inv;
        aw_out[(size_t)b * T_ + t]  = a;
        cov_out[(size_t)b * T_ + t] = a + pc[t];
    }
}

// ============================================================================
// context partials + reduce
// ============================================================================
__global__ void ctx_part_kernel(const float* __restrict__ values,
                                const float* __restrict__ aw) {
    const int tc = blockIdx.x, b = blockIdx.y, tid = threadIdx.x;
    __shared__ float sa[128];
    const int t0 = tc * 128;
    if (tid < 128) sa[tid] = aw[(size_t)b * T_ + t0 + tid];
    __syncthreads();

    const float4* vp = (const float4*)(values) + ((size_t)b * T_ + t0) * (D_ / 4) + tid;
    float4 acc = make_float4(0.f, 0.f, 0.f, 0.f);
    #pragma unroll 4
    for (int t = 0; t < 128; ++t) {
        float4 v = vp[(size_t)t * (D_ / 4)];
        float a = sa[t];
        acc.x = fmaf(a, v.x, acc.x);
        acc.y = fmaf(a, v.y, acc.y);
        acc.z = fmaf(a, v.z, acc.z);
        acc.w = fmaf(a, v.w, acc.w);
    }
    ((float4*)g_ctxpart)[((size_t)tc * B_ + b) * (D_ / 4) + tid] = acc;
}

__global__ void ctx_reduce_kernel(float* __restrict__ out) {
    int g = blockIdx.x * blockDim.x + threadIdx.x;
    float s = 0.0f;
    #pragma unroll
    for (int tc = 0; tc < NCTX; ++tc)
        s += g_ctxpart[(size_t)tc * B_ * D_ + g];
    out[g] = s;
}

// ============================================================================
extern "C" void kernel_launch(void* const* d_in, const int* in_sizes, int n_in,
                              void* d_out, int out_size) {
    const float* query    = (const float*)d_in[0];
    const float* values   = (const float*)d_in[1];
    const float* prev_cov = (const float*)d_in[2];
    const float* Wh       = (const float*)d_in[3];
    const float* bh       = (const float*)d_in[4];
    const float* Ws       = (const float*)d_in[5];
    const float* bs       = (const float*)d_in[6];
    const float* Wc       = (const float*)d_in[7];
    const float* bc       = (const float*)d_in[8];
    const float* Vw       = (const float*)d_in[9];
    const float* Vb       = (const float*)d_in[10];
    float* out = (float*)d_out;

    cudaFuncSetAttribute(score_gemm_kernel,
                         cudaFuncAttributeMaxDynamicSharedMemorySize, GEMM_SMEM);

    conv_values_kernel<<<(int)((size_t)M_ * D_ / 4 / 256), 256>>>(values);
    conv_ws_kernel<<<dim3(32, 32), dim3(32, 8)>>>(Ws);
    qproj_part_kernel<<<dim3(128, KS_), 256>>>(query, Wh, bh, bs, bc);
    score_gemm_kernel<<<M_ / 128, 256, GEMM_SMEM>>>(prev_cov, Wc, Vw);
    softmax_kernel<<<B_, 256>>>(prev_cov, Vb, out);
    ctx_part_kernel<<<dim3(NCTX, B_), 256>>>(values, out + B_ * D_);
    ctx_reduce_kernel<<<(B_ * D_) / 256, 256>>>(out);
}

// round 10
// speedup vs baseline: 1.4769x; 1.4769x over previous
#include <cuda_runtime.h>
#include <cuda_fp16.h>
#include <math.h>
#include <stdint.h>

#define B_  32
#define T_  2048
#define D_  1024
#define M_  (B_ * T_)
#define NCTX 16
#define KS_  4

// ---------------- scratch (static device globals; no allocation) ----------------
__device__ __half g_vhi[(size_t)M_ * D_];     // 128 MB
__device__ __half g_vlo[(size_t)M_ * D_];     // 128 MB (A residual)
__device__ __half g_wshi[(size_t)D_ * D_];    // Ws^T: [n][k], single fp16
__device__ float g_qpart[KS_ * B_ * D_];
__device__ float g_score[M_];
__device__ float g_ctxpart[NCTX * B_ * D_];

// ---------------- PTX helpers ----------------
__device__ __forceinline__ uint32_t smem_u32(const void* p) {
    uint32_t a;
    asm("{ .reg .u64 t; cvta.to.shared.u64 t, %1; cvt.u32.u64 %0, t; }" : "=r"(a) : "l"(p));
    return a;
}
__device__ __forceinline__ void cp_async16(uint32_t dst, const void* src) {
    asm volatile("cp.async.cg.shared.global [%0], [%1], 16;" :: "r"(dst), "l"(src));
}
#define CP_COMMIT asm volatile("cp.async.commit_group;" ::: "memory")
#define CP_WAIT1  asm volatile("cp.async.wait_group 1;" ::: "memory")
#define CP_WAIT0  asm volatile("cp.async.wait_group 0;" ::: "memory")

__device__ __forceinline__ void ldsm4(uint32_t* r, uint32_t addr) {
    asm volatile("ldmatrix.sync.aligned.m8n8.x4.shared.b16 {%0,%1,%2,%3}, [%4];"
        : "=r"(r[0]), "=r"(r[1]), "=r"(r[2]), "=r"(r[3]) : "r"(addr));
}
__device__ __forceinline__ void mma_f32(float* d, const uint32_t* a, uint32_t b0, uint32_t b1) {
    asm("mma.sync.aligned.m16n8k16.row.col.f32.f16.f16.f32 "
        "{%0,%1,%2,%3}, {%4,%5,%6,%7}, {%8,%9}, {%0,%1,%2,%3};"
        : "+f"(d[0]), "+f"(d[1]), "+f"(d[2]), "+f"(d[3])
        : "r"(a[0]), "r"(a[1]), "r"(a[2]), "r"(a[3]), "r"(b0), "r"(b1));
}

// ============================================================================
// conversions: values -> fp16 hi/lo split; Ws -> transposed fp16 (hi only)
// ============================================================================
__global__ void conv_values_kernel(const float* __restrict__ v) {
    size_t g = (size_t)blockIdx.x * 256 + threadIdx.x;   // float4 index
    float4 x = ((const float4*)v)[g];
    __half h0 = __float2half_rn(x.x), h1 = __float2half_rn(x.y);
    __half h2 = __float2half_rn(x.z), h3 = __float2half_rn(x.w);
    __half l0 = __float2half_rn(x.x - __half2float(h0));
    __half l1 = __float2half_rn(x.y - __half2float(h1));
    __half l2 = __float2half_rn(x.z - __half2float(h2));
    __half l3 = __float2half_rn(x.w - __half2float(h3));
    __half2 p;
    p.x = h0; p.y = h1; ((__half2*)g_vhi)[g * 2]     = p;
    p.x = h2; p.y = h3; ((__half2*)g_vhi)[g * 2 + 1] = p;
    p.x = l0; p.y = l1; ((__half2*)g_vlo)[g * 2]     = p;
    p.x = l2; p.y = l3; ((__half2*)g_vlo)[g * 2 + 1] = p;
}

__global__ void conv_ws_kernel(const float* __restrict__ Ws) {
    __shared__ float tile[32][33];
    const int n0 = blockIdx.x * 32, k0 = blockIdx.y * 32;
    const int tx = threadIdx.x, ty = threadIdx.y;     // (32, 8)
    #pragma unroll
    for (int i = 0; i < 32; i += 8)
        tile[ty + i][tx] = Ws[(size_t)(k0 + ty + i) * D_ + n0 + tx];
    __syncthreads();
    #pragma unroll
    for (int i = 0; i < 32; i += 8)
        g_wshi[(size_t)(n0 + ty + i) * D_ + k0 + tx] = __float2half_rn(tile[tx][ty + i]);
}

// ============================================================================
// qproj partials (k-split x4); summed during GEMM epilogue staging
// ============================================================================
__global__ void qproj_part_kernel(const float* __restrict__ query,
                                  const float* __restrict__ Wh,
                                  const float* __restrict__ bh,
                                  const float* __restrict__ bs,
                                  const float* __restrict__ bc) {
    int g  = blockIdx.x * 256 + threadIdx.x;     // 32768
    int ks = blockIdx.y;
    int u = g & (D_ - 1);
    int b = g >> 10;
    float acc = (ks == 0) ? (bh[u] + bs[u] + bc[u]) : 0.0f;
    const float* q = query + (size_t)b * D_;
    int kbeg = ks * (D_ / KS_), kend = kbeg + D_ / KS_;
    #pragma unroll 8
    for (int k = kbeg; k < kend; ++k)
        acc = fmaf(q[k], Wh[(size_t)k * D_ + u], acc);
    g_qpart[(size_t)ks * B_ * D_ + g] = acc;
}

// ============================================================================
// score GEMM: CTA = 128M x 128N subtile (loop ns=0..7 covers N=1024).
// 8 warps, warp tile 64x32, 2 CTAs/SM. fp16 2-term split (A split, B single):
//   act = ah*bh + al*bh   (dropped A*deltaB ~ 2^-12)
// 3-stage cp.async pipeline, XOR-swizzled 64B-pitch smem, ldmatrix loads.
// ============================================================================
#define BUF_B 24576                 // AH 8K | AL 8K | BH 8K
#define O_AL  8192
#define O_BH  16384
#define NSTAGE 3
#define EPI_OFF (NSTAGE * BUF_B)    // 73728
#define GEMM_SMEM (EPI_OFF + (512 + 512) * 4)   // 77824

__global__ __launch_bounds__(256, 2)
void score_gemm_kernel(const float* __restrict__ prev_cov,
                       const float* __restrict__ Wc,
                       const float* __restrict__ Vw) {
    extern __shared__ char smem[];
    const uint32_t sb = smem_u32(smem);
    float* qb_s = (float*)(smem + EPI_OFF);          // 128
    float* wc_s = qb_s + 128;
    float* vw_s = qb_s + 256;
    float* pc_s = qb_s + 384;                        // 128
    float (*Red)[4] = (float(*)[4])(qb_s + 512);     // [128][4]

    const int tid  = threadIdx.x;
    const int wid  = tid >> 5;
    const int lane = tid & 31;
    const int wm   = (wid >> 2) * 64;                // 0 / 64
    const int wn   = (wid & 3) * 32;                 // 0..96

    const int m0  = blockIdx.x * 128;
    const int b   = blockIdx.x >> 4;
    const int tt0 = (blockIdx.x & 15) * 128;

    if (tid < 128) pc_s[tid] = prev_cov[(size_t)b * T_ + tt0 + tid];

    // ---- hoisted fragment addressing (kk=16 differs by ^0x20) ----
    const int lr  = (lane & 7) + (lane & 8);
    const uint32_t k8 = lane >> 4;                   // 0/1
    uint32_t aoff[4], boff[2];
    #pragma unroll
    for (int mf = 0; mf < 4; ++mf) {
        int r = wm + mf * 16 + lr;
        aoff[mf] = (uint32_t)(r << 6) + (((k8 ^ (r >> 1)) & 3) << 4);
    }
    #pragma unroll
    for (int p = 0; p < 2; ++p) {
        int n = wn + p * 16 + lr;
        boff[p] = (uint32_t)(n << 6) + (((k8 ^ (n >> 1)) & 3) << 4) + O_BH;
    }

    float sacc[4][2];
    #pragma unroll
    for (int mf = 0; mf < 4; ++mf) { sacc[mf][0] = 0.f; sacc[mf][1] = 0.f; }

    // per-chunk loads: A hi/lo + B hi; 6 cp.async per thread
    #define ISSUE_CHUNK(c, bi, ns) do {                                        \
        uint32_t bb_ = sb + (bi) * BUF_B;                                      \
        _Pragma("unroll")                                                      \
        for (int i_ = 0; i_ < 2; ++i_) {                                       \
            int idx_ = tid + 256 * i_; int r_ = idx_ >> 2, u_ = idx_ & 3;      \
            uint32_t d_ = bb_ + (r_ << 6) + (((u_ ^ ((r_ >> 1) & 3)) & 3) << 4); \
            size_t ga_ = (size_t)(m0 + r_) * D_ + (c) * 32 + u_ * 8;           \
            size_t gb_ = (size_t)((ns) * 128 + r_) * D_ + (c) * 32 + u_ * 8;   \
            cp_async16(d_,        g_vhi + ga_);                                \
            cp_async16(d_ + O_AL, g_vlo + ga_);                                \
            cp_async16(d_ + O_BH, g_wshi + gb_);                               \
        }                                                                      \
        CP_COMMIT;                                                             \
    } while (0)

    for (int ns = 0; ns < 8; ++ns) {
        // stage epilogue constants for this subtile
        if (tid < 128) {
            int n = ns * 128 + tid;
            float q = g_qpart[(size_t)b * D_ + n]
                    + g_qpart[(size_t)B_ * D_ + (size_t)b * D_ + n]
                    + g_qpart[(size_t)2 * B_ * D_ + (size_t)b * D_ + n]
                    + g_qpart[(size_t)3 * B_ * D_ + (size_t)b * D_ + n];
            qb_s[tid] = q;
            wc_s[tid] = Wc[n];
            vw_s[tid] = Vw[n];
        }

        float acc[4][4][4];
        #pragma unroll
        for (int i = 0; i < 4; ++i)
            #pragma unroll
            for (int j = 0; j < 4; ++j)
                #pragma unroll
                for (int r = 0; r < 4; ++r) acc[i][j][r] = 0.0f;

        ISSUE_CHUNK(0, 0, ns);
        ISSUE_CHUNK(1, 1, ns);

        for (int c = 0; c < 32; ++c) {
            if (c + 1 < 32) CP_WAIT1; else CP_WAIT0;   // chunk c resident
            __syncthreads();
            if (c + 2 < 32) ISSUE_CHUNK(c + 2, (c + 2) % NSTAGE, ns);

            const uint32_t bb = sb + (c % NSTAGE) * BUF_B;
            #pragma unroll
            for (int kk = 0; kk < 32; kk += 16) {
                const uint32_t xm = kk ? 0x20u : 0u;
                uint32_t af[4][4], bf[2][4];
                // A_hi + B_hi batches
                #pragma unroll
                for (int mf = 0; mf < 4; ++mf) ldsm4(af[mf], (bb + aoff[mf]) ^ xm);
                #pragma unroll
                for (int p = 0; p < 2; ++p) ldsm4(bf[p], (bb + boff[p]) ^ xm);
                // hh
                #pragma unroll
                for (int mf = 0; mf < 4; ++mf)
                    #pragma unroll
                    for (int p = 0; p < 2; ++p) {
                        mma_f32(acc[mf][2 * p],     af[mf], bf[p][0], bf[p][2]);
                        mma_f32(acc[mf][2 * p + 1], af[mf], bf[p][1], bf[p][3]);
                    }
                // A_lo (overwrite af); lh
                #pragma unroll
                for (int mf = 0; mf < 4; ++mf) ldsm4(af[mf], (bb + aoff[mf] + O_AL) ^ xm);
                #pragma unroll
                for (int mf = 0; mf < 4; ++mf)
                    #pragma unroll
                    for (int p = 0; p < 2; ++p) {
                        mma_f32(acc[mf][2 * p],     af[mf], bf[p][0], bf[p][2]);
                        mma_f32(acc[mf][2 * p + 1], af[mf], bf[p][1], bf[p][3]);
                    }
            }
        }

        // fused epilogue for this subtile
        #pragma unroll
        for (int mf = 0; mf < 4; ++mf) {
            const int rA = wm + mf * 16 + (lane >> 2);
            const float pA = pc_s[rA], pB = pc_s[rA + 8];
            float sA = 0.f, sB = 0.f;
            #pragma unroll
            for (int nf = 0; nf < 4; ++nf) {
                int c0 = wn + nf * 8 + 2 * (lane & 3);
                int c1 = c0 + 1;
                sA += tanhf(acc[mf][nf][0] + qb_s[c0] + pA * wc_s[c0]) * vw_s[c0];
                sA += tanhf(acc[mf][nf][1] + qb_s[c1] + pA * wc_s[c1]) * vw_s[c1];
                sB += tanhf(acc[mf][nf][2] + qb_s[c0] + pB * wc_s[c0]) * vw_s[c0];
                sB += tanhf(acc[mf][nf][3] + qb_s[c1] + pB * wc_s[c1]) * vw_s[c1];
            }
            sacc[mf][0] += sA;
            sacc[mf][1] += sB;
        }
        __syncthreads();   // before next subtile overwrites qb_s/wc_s/vw_s
    }

    // reduce over lanes (n quads) and warps (n-warps), write final scores
    #pragma unroll
    for (int mf = 0; mf < 4; ++mf) {
        float sA = sacc[mf][0], sB = sacc[mf][1];
        sA += __shfl_xor_sync(0xffffffff, sA, 1);
        sA += __shfl_xor_sync(0xffffffff, sA, 2);
        sB += __shfl_xor_sync(0xffffffff, sB, 1);
        sB += __shfl_xor_sync(0xffffffff, sB, 2);
        if ((lane & 3) == 0) {
            int rA = wm + mf * 16 + (lane >> 2);
            Red[rA][wid & 3]     = sA;
            Red[rA + 8][wid & 3] = sB;
        }
    }
    __syncthreads();
    if (tid < 128) {
        g_score[(size_t)m0 + tid] = Red[tid][0] + Red[tid][1] + Red[tid][2] + Red[tid][3];
    }
}

// ============================================================================
// softmax over T per batch; writes attention_weights + coverage
// ============================================================================
__global__ void softmax_kernel(const float* __restrict__ prev_cov,
                               const float* __restrict__ Vb,
                               float* __restrict__ out) {
    __shared__ float sc[T_];
    __shared__ float red[256];
    const int b = blockIdx.x;
    const int tid = threadIdx.x;
    const float vb = Vb[0];

    float lmax = -1e30f;
    for (int t = tid; t < T_; t += 256) {
        float s = g_score[(size_t)b * T_ + t] + vb;
        sc[t] = s;
        lmax = fmaxf(lmax, s);
    }
    red[tid] = lmax;
    __syncthreads();
    for (int st = 128; st > 0; st >>= 1) {
        if (tid < st) red[tid] = fmaxf(red[tid], red[tid + st]);
        __syncthreads();
    }
    const float mx = red[0];
    __syncthreads();

    float lsum = 0.0f;
    for (int t = tid; t < T_; t += 256) {
        float e = expf(sc[t] - mx);
        sc[t] = e;
        lsum += e;
    }
    red[tid] = lsum;
    __syncthreads();
    for (int st = 128; st > 0; st >>= 1) {
        if (tid < st) red[tid] += red[tid + st];
        __syncthreads();
    }
    const float inv = 1.0f / red[0];

    float* aw_out  = out + B_ * D_;
    float* cov_out = out + B_ * D_ + B_ * T_;
    const float* pc = prev_cov + (size_t)b * T_;
    for (int t = tid; t < T_; t += 256) {
        float a = sc[t] * inv;
        aw_out[(size_t)b * T_ + t]  = a;
        cov_out[(size_t)b * T_ + t] = a + pc[t];
    }
}

// ============================================================================
// context partials + reduce
// ============================================================================
__global__ void ctx_part_kernel(const float* __restrict__ values,
                                const float* __restrict__ aw) {
    const int tc = blockIdx.x, b = blockIdx.y, tid = threadIdx.x;
    __shared__ float sa[128];
    const int t0 = tc * 128;
    if (tid < 128) sa[tid] = aw[(size_t)b * T_ + t0 + tid];
    __syncthreads();

    const float4* vp = (const float4*)(values) + ((size_t)b * T_ + t0) * (D_ / 4) + tid;
    float4 acc = make_float4(0.f, 0.f, 0.f, 0.f);
    #pragma unroll 4
    for (int t = 0; t < 128; ++t) {
        float4 v = vp[(size_t)t * (D_ / 4)];
        float a = sa[t];
        acc.x = fmaf(a, v.x, acc.x);
        acc.y = fmaf(a, v.y, acc.y);
        acc.z = fmaf(a, v.z, acc.z);
        acc.w = fmaf(a, v.w, acc.w);
    }
    ((float4*)g_ctxpart)[((size_t)tc * B_ + b) * (D_ / 4) + tid] = acc;
}

__global__ void ctx_reduce_kernel(float* __restrict__ out) {
    int g = blockIdx.x * blockDim.x + threadIdx.x;
    float s = 0.0f;
    #pragma unroll
    for (int tc = 0; tc < NCTX; ++tc)
        s += g_ctxpart[(size_t)tc * B_ * D_ + g];
    out[g] = s;
}

// ============================================================================
extern "C" void kernel_launch(void* const* d_in, const int* in_sizes, int n_in,
                              void* d_out, int out_size) {
    const float* query    = (const float*)d_in[0];
    const float* values   = (const float*)d_in[1];
    const float* prev_cov = (const float*)d_in[2];
    const float* Wh       = (const float*)d_in[3];
    const float* bh       = (const float*)d_in[4];
    const float* Ws       = (const float*)d_in[5];
    const float* bs       = (const float*)d_in[6];
    const float* Wc       = (const float*)d_in[7];
    const float* bc       = (const float*)d_in[8];
    const float* Vw       = (const float*)d_in[9];
    const float* Vb       = (const float*)d_in[10];
    float* out = (float*)d_out;

    cudaFuncSetAttribute(score_gemm_kernel,
                         cudaFuncAttributeMaxDynamicSharedMemorySize, GEMM_SMEM);

    conv_values_kernel<<<(int)((size_t)M_ * D_ / 4 / 256), 256>>>(values);
    conv_ws_kernel<<<dim3(32, 32), dim3(32, 8)>>>(Ws);
    qproj_part_kernel<<<dim3(128, KS_), 256>>>(query, Wh, bh, bs, bc);
    score_gemm_kernel<<<M_ / 128, 256, GEMM_SMEM>>>(prev_cov, Wc, Vw);
    softmax_kernel<<<B_, 256>>>(prev_cov, Vb, out);
    ctx_part_kernel<<<dim3(NCTX, B_), 256>>>(values, out + B_ * D_);
    ctx_reduce_kernel<<<(B_ * D_) / 256, 256>>>(out);
}

// round 11
// speedup vs baseline: 2.4118x; 1.6330x over previous
#include <cuda_runtime.h>
#include <cuda_fp16.h>
#include <math.h>
#include <stdint.h>

#define B_  32
#define T_  2048
#define D_  1024
#define M_  (B_ * T_)
#define NCTX 16
#define KS_  4

// ---------------- scratch (static device globals; no allocation) ----------------
__device__ __half g_vhi[(size_t)M_ * D_];     // 128 MB
__device__ __half g_wshi[(size_t)D_ * D_];    // Ws^T: [n][k], fp16
__device__ float g_qpart[KS_ * B_ * D_];
__device__ float g_score[M_];
__device__ float g_ctxpart[NCTX * B_ * D_];

// ---------------- PTX helpers ----------------
__device__ __forceinline__ uint32_t smem_u32(const void* p) {
    uint32_t a;
    asm("{ .reg .u64 t; cvta.to.shared.u64 t, %1; cvt.u32.u64 %0, t; }" : "=r"(a) : "l"(p));
    return a;
}
__device__ __forceinline__ void cp_async16(uint32_t dst, const void* src) {
    asm volatile("cp.async.cg.shared.global [%0], [%1], 16;" :: "r"(dst), "l"(src));
}
#define CP_COMMIT asm volatile("cp.async.commit_group;" ::: "memory")
#define CP_WAIT1  asm volatile("cp.async.wait_group 1;" ::: "memory")
#define CP_WAIT0  asm volatile("cp.async.wait_group 0;" ::: "memory")

__device__ __forceinline__ void ldsm4(uint32_t* r, uint32_t addr) {
    asm volatile("ldmatrix.sync.aligned.m8n8.x4.shared.b16 {%0,%1,%2,%3}, [%4];"
        : "=r"(r[0]), "=r"(r[1]), "=r"(r[2]), "=r"(r[3]) : "r"(addr));
}
__device__ __forceinline__ void mma_f32(float* d, const uint32_t* a, uint32_t b0, uint32_t b1) {
    asm("mma.sync.aligned.m16n8k16.row.col.f32.f16.f16.f32 "
        "{%0,%1,%2,%3}, {%4,%5,%6,%7}, {%8,%9}, {%0,%1,%2,%3};"
        : "+f"(d[0]), "+f"(d[1]), "+f"(d[2]), "+f"(d[3])
        : "r"(a[0]), "r"(a[1]), "r"(a[2]), "r"(a[3]), "r"(b0), "r"(b1));
}

// ============================================================================
// conversions: values -> fp16; Ws -> transposed fp16
// ============================================================================
__global__ void conv_values_kernel(const float* __restrict__ v) {
    size_t g = (size_t)blockIdx.x * 256 + threadIdx.x;   // float4 index
    float4 x = ((const float4*)v)[g];
    __half2 p;
    p.x = __float2half_rn(x.x); p.y = __float2half_rn(x.y);
    ((__half2*)g_vhi)[g * 2]     = p;
    p.x = __float2half_rn(x.z); p.y = __float2half_rn(x.w);
    ((__half2*)g_vhi)[g * 2 + 1] = p;
}

__global__ void conv_ws_kernel(const float* __restrict__ Ws) {
    __shared__ float tile[32][33];
    const int n0 = blockIdx.x * 32, k0 = blockIdx.y * 32;
    const int tx = threadIdx.x, ty = threadIdx.y;     // (32, 8)
    #pragma unroll
    for (int i = 0; i < 32; i += 8)
        tile[ty + i][tx] = Ws[(size_t)(k0 + ty + i) * D_ + n0 + tx];
    __syncthreads();
    #pragma unroll
    for (int i = 0; i < 32; i += 8)
        g_wshi[(size_t)(n0 + ty + i) * D_ + k0 + tx] = __float2half_rn(tile[tx][ty + i]);
}

// ============================================================================
// qproj partials (k-split x4); summed during GEMM epilogue staging
// ============================================================================
__global__ void qproj_part_kernel(const float* __restrict__ query,
                                  const float* __restrict__ Wh,
                                  const float* __restrict__ bh,
                                  const float* __restrict__ bs,
                                  const float* __restrict__ bc) {
    int g  = blockIdx.x * 256 + threadIdx.x;     // 32768
    int ks = blockIdx.y;
    int u = g & (D_ - 1);
    int b = g >> 10;
    float acc = (ks == 0) ? (bh[u] + bs[u] + bc[u]) : 0.0f;
    const float* q = query + (size_t)b * D_;
    int kbeg = ks * (D_ / KS_), kend = kbeg + D_ / KS_;
    #pragma unroll 8
    for (int k = kbeg; k < kend; ++k)
        acc = fmaf(q[k], Wh[(size_t)k * D_ + u], acc);
    g_qpart[(size_t)ks * B_ * D_ + g] = acc;
}

// ============================================================================
// score GEMM: CTA = 128M x 128N subtile (loop ns=0..7 covers N=1024).
// 8 warps, warp tile 64x32, 2 CTAs/SM. Pure fp16 inputs, fp32 accumulate.
// 3-stage cp.async pipeline, XOR-swizzled 64B-pitch smem, ldmatrix loads.
// ============================================================================
#define BUF_B 16384                 // A 8K | B 8K
#define O_BH  8192
#define NSTAGE 3
#define EPI_OFF (NSTAGE * BUF_B)    // 49152
#define GEMM_SMEM (EPI_OFF + (512 + 512) * 4)   // 53248

__global__ __launch_bounds__(256, 2)
void score_gemm_kernel(const float* __restrict__ prev_cov,
                       const float* __restrict__ Wc,
                       const float* __restrict__ Vw) {
    extern __shared__ char smem[];
    const uint32_t sb = smem_u32(smem);
    float* qb_s = (float*)(smem + EPI_OFF);          // 128
    float* wc_s = qb_s + 128;
    float* vw_s = qb_s + 256;
    float* pc_s = qb_s + 384;                        // 128
    float (*Red)[4] = (float(*)[4])(qb_s + 512);     // [128][4]

    const int tid  = threadIdx.x;
    const int wid  = tid >> 5;
    const int lane = tid & 31;
    const int wm   = (wid >> 2) * 64;                // 0 / 64
    const int wn   = (wid & 3) * 32;                 // 0..96

    const int m0  = blockIdx.x * 128;
    const int b   = blockIdx.x >> 4;
    const int tt0 = (blockIdx.x & 15) * 128;

    if (tid < 128) pc_s[tid] = prev_cov[(size_t)b * T_ + tt0 + tid];

    // ---- hoisted fragment addressing (kk=16 differs by ^0x20) ----
    const int lr  = (lane & 7) + (lane & 8);
    const uint32_t k8 = lane >> 4;                   // 0/1
    uint32_t aoff[4], boff[2];
    #pragma unroll
    for (int mf = 0; mf < 4; ++mf) {
        int r = wm + mf * 16 + lr;
        aoff[mf] = (uint32_t)(r << 6) + (((k8 ^ (r >> 1)) & 3) << 4);
    }
    #pragma unroll
    for (int p = 0; p < 2; ++p) {
        int n = wn + p * 16 + lr;
        boff[p] = (uint32_t)(n << 6) + (((k8 ^ (n >> 1)) & 3) << 4) + O_BH;
    }

    float sacc[4][2];
    #pragma unroll
    for (int mf = 0; mf < 4; ++mf) { sacc[mf][0] = 0.f; sacc[mf][1] = 0.f; }

    // per-chunk loads: A + B; 4 cp.async per thread
    #define ISSUE_CHUNK(c, bi, ns) do {                                        \
        uint32_t bb_ = sb + (bi) * BUF_B;                                      \
        _Pragma("unroll")                                                      \
        for (int i_ = 0; i_ < 2; ++i_) {                                       \
            int idx_ = tid + 256 * i_; int r_ = idx_ >> 2, u_ = idx_ & 3;      \
            uint32_t d_ = bb_ + (r_ << 6) + (((u_ ^ ((r_ >> 1) & 3)) & 3) << 4); \
            size_t ga_ = (size_t)(m0 + r_) * D_ + (c) * 32 + u_ * 8;           \
            size_t gb_ = (size_t)((ns) * 128 + r_) * D_ + (c) * 32 + u_ * 8;   \
            cp_async16(d_,        g_vhi + ga_);                                \
            cp_async16(d_ + O_BH, g_wshi + gb_);                               \
        }                                                                      \
        CP_COMMIT;                                                             \
    } while (0)

    for (int ns = 0; ns < 8; ++ns) {
        // stage epilogue constants for this subtile
        if (tid < 128) {
            int n = ns * 128 + tid;
            float q = g_qpart[(size_t)b * D_ + n]
                    + g_qpart[(size_t)B_ * D_ + (size_t)b * D_ + n]
                    + g_qpart[(size_t)2 * B_ * D_ + (size_t)b * D_ + n]
                    + g_qpart[(size_t)3 * B_ * D_ + (size_t)b * D_ + n];
            qb_s[tid] = q;
            wc_s[tid] = Wc[n];
            vw_s[tid] = Vw[n];
        }

        float acc[4][4][4];
        #pragma unroll
        for (int i = 0; i < 4; ++i)
            #pragma unroll
            for (int j = 0; j < 4; ++j)
                #pragma unroll
                for (int r = 0; r < 4; ++r) acc[i][j][r] = 0.0f;

        ISSUE_CHUNK(0, 0, ns);
        ISSUE_CHUNK(1, 1, ns);

        for (int c = 0; c < 32; ++c) {
            if (c + 1 < 32) CP_WAIT1; else CP_WAIT0;   // chunk c resident
            __syncthreads();
            if (c + 2 < 32) ISSUE_CHUNK(c + 2, (c + 2) % NSTAGE, ns);

            const uint32_t bb = sb + (c % NSTAGE) * BUF_B;
            #pragma unroll
            for (int kk = 0; kk < 32; kk += 16) {
                const uint32_t xm = kk ? 0x20u : 0u;
                uint32_t af[4][4], bf[2][4];
                #pragma unroll
                for (int mf = 0; mf < 4; ++mf) ldsm4(af[mf], (bb + aoff[mf]) ^ xm);
                #pragma unroll
                for (int p = 0; p < 2; ++p) ldsm4(bf[p], (bb + boff[p]) ^ xm);
                #pragma unroll
                for (int mf = 0; mf < 4; ++mf)
                    #pragma unroll
                    for (int p = 0; p < 2; ++p) {
                        mma_f32(acc[mf][2 * p],     af[mf], bf[p][0], bf[p][2]);
                        mma_f32(acc[mf][2 * p + 1], af[mf], bf[p][1], bf[p][3]);
                    }
            }
        }

        // fused epilogue for this subtile
        #pragma unroll
        for (int mf = 0; mf < 4; ++mf) {
            const int rA = wm + mf * 16 + (lane >> 2);
            const float pA = pc_s[rA], pB = pc_s[rA + 8];
            float sA = 0.f, sB = 0.f;
            #pragma unroll
            for (int nf = 0; nf < 4; ++nf) {
                int c0 = wn + nf * 8 + 2 * (lane & 3);
                int c1 = c0 + 1;
                sA += tanhf(acc[mf][nf][0] + qb_s[c0] + pA * wc_s[c0]) * vw_s[c0];
                sA += tanhf(acc[mf][nf][1] + qb_s[c1] + pA * wc_s[c1]) * vw_s[c1];
                sB += tanhf(acc[mf][nf][2] + qb_s[c0] + pB * wc_s[c0]) * vw_s[c0];
                sB += tanhf(acc[mf][nf][3] + qb_s[c1] + pB * wc_s[c1]) * vw_s[c1];
            }
            sacc[mf][0] += sA;
            sacc[mf][1] += sB;
        }
        __syncthreads();   // before next subtile overwrites qb_s/wc_s/vw_s
    }

    // reduce over lanes (n quads) and warps (n-warps), write final scores
    #pragma unroll
    for (int mf = 0; mf < 4; ++mf) {
        float sA = sacc[mf][0], sB = sacc[mf][1];
        sA += __shfl_xor_sync(0xffffffff, sA, 1);
        sA += __shfl_xor_sync(0xffffffff, sA, 2);
        sB += __shfl_xor_sync(0xffffffff, sB, 1);
        sB += __shfl_xor_sync(0xffffffff, sB, 2);
        if ((lane & 3) == 0) {
            int rA = wm + mf * 16 + (lane >> 2);
            Red[rA][wid & 3]     = sA;
            Red[rA + 8][wid & 3] = sB;
        }
    }
    __syncthreads();
    if (tid < 128) {
        g_score[(size_t)m0 + tid] = Red[tid][0] + Red[tid][1] + Red[tid][2] + Red[tid][3];
    }
}

// ============================================================================
// softmax over T per batch; writes attention_weights + coverage
// ============================================================================
__global__ void softmax_kernel(const float* __restrict__ prev_cov,
                               const float* __restrict__ Vb,
                               float* __restrict__ out) {
    __shared__ float sc[T_];
    __shared__ float red[256];
    const int b = blockIdx.x;
    const int tid = threadIdx.x;
    const float vb = Vb[0];

    float lmax = -1e30f;
    for (int t = tid; t < T_; t += 256) {
        float s = g_score[(size_t)b * T_ + t] + vb;
        sc[t] = s;
        lmax = fmaxf(lmax, s);
    }
    red[tid] = lmax;
    __syncthreads();
    for (int st = 128; st > 0; st >>= 1) {
        if (tid < st) red[tid] = fmaxf(red[tid], red[tid + st]);
        __syncthreads();
    }
    const float mx = red[0];
    __syncthreads();

    float lsum = 0.0f;
    for (int t = tid; t < T_; t += 256) {
        float e = expf(sc[t] - mx);
        sc[t] = e;
        lsum += e;
    }
    red[tid] = lsum;
    __syncthreads();
    for (int st = 128; st > 0; st >>= 1) {
        if (tid < st) red[tid] += red[tid + st];
        __syncthreads();
    }
    const float inv = 1.0f / red[0];

    float* aw_out  = out + B_ * D_;
    float* cov_out = out + B_ * D_ + B_ * T_;
    const float* pc = prev_cov + (size_t)b * T_;
    for (int t = tid; t < T_; t += 256) {
        float a = sc[t] * inv;
        aw_out[(size_t)b * T_ + t]  = a;
        cov_out[(size_t)b * T_ + t] = a + pc[t];
    }
}

// ============================================================================
// context partials + reduce
// ============================================================================
__global__ void ctx_part_kernel(const float* __restrict__ values,
                                const float* __restrict__ aw) {
    const int tc = blockIdx.x, b = blockIdx.y, tid = threadIdx.x;
    __shared__ float sa[128];
    const int t0 = tc * 128;
    if (tid < 128) sa[tid] = aw[(size_t)b * T_ + t0 + tid];
    __syncthreads();

    const float4* vp = (const float4*)(values) + ((size_t)b * T_ + t0) * (D_ / 4) + tid;
    float4 acc = make_float4(0.f, 0.f, 0.f, 0.f);
    #pragma unroll 4
    for (int t = 0; t < 128; ++t) {
        float4 v = vp[(size_t)t * (D_ / 4)];
        float a = sa[t];
        acc.x = fmaf(a, v.x, acc.x);
        acc.y = fmaf(a, v.y, acc.y);
        acc.z = fmaf(a, v.z, acc.z);
        acc.w = fmaf(a, v.w, acc.w);
    }
    ((float4*)g_ctxpart)[((size_t)tc * B_ + b) * (D_ / 4) + tid] = acc;
}

__global__ void ctx_reduce_kernel(float* __restrict__ out) {
    int g = blockIdx.x * blockDim.x + threadIdx.x;
    float s = 0.0f;
    #pragma unroll
    for (int tc = 0; tc < NCTX; ++tc)
        s += g_ctxpart[(size_t)tc * B_ * D_ + g];
    out[g] = s;
}

// ============================================================================
extern "C" void kernel_launch(void* const* d_in, const int* in_sizes, int n_in,
                              void* d_out, int out_size) {
    const float* query    = (const float*)d_in[0];
    const float* values   = (const float*)d_in[1];
    const float* prev_cov = (const float*)d_in[2];
    const float* Wh       = (const float*)d_in[3];
    const float* bh       = (const float*)d_in[4];
    const float* Ws       = (const float*)d_in[5];
    const float* bs       = (const float*)d_in[6];
    const float* Wc       = (const float*)d_in[7];
    const float* bc       = (const float*)d_in[8];
    const float* Vw       = (const float*)d_in[9];
    const float* Vb       = (const float*)d_in[10];
    float* out = (float*)d_out;

    cudaFuncSetAttribute(score_gemm_kernel,
                         cudaFuncAttributeMaxDynamicSharedMemorySize, GEMM_SMEM);

    conv_values_kernel<<<(int)((size_t)M_ * D_ / 4 / 256), 256>>>(values);
    conv_ws_kernel<<<dim3(32, 32), dim3(32, 8)>>>(Ws);
    qproj_part_kernel<<<dim3(128, KS_), 256>>>(query, Wh, bh, bs, bc);
    score_gemm_kernel<<<M_ / 128, 256, GEMM_SMEM>>>(prev_cov, Wc, Vw);
    softmax_kernel<<<B_, 256>>>(prev_cov, Vb, out);
    ctx_part_kernel<<<dim3(NCTX, B_), 256>>>(values, out + B_ * D_);
    ctx_reduce_kernel<<<(B_ * D_) / 256, 256>>>(out);
}

// round 12
// speedup vs baseline: 2.6289x; 1.0900x over previous
#include <cuda_runtime.h>
#include <cuda_fp16.h>
#include <math.h>
#include <stdint.h>

#define B_  32
#define T_  2048
#define D_  1024
#define M_  (B_ * T_)
#define NCTX 16
#define KS_  4

// ---------------- scratch (static device globals; no allocation) ----------------
// chunk-major, pre-swizzled: block (c, m) at (c*M_ + m)*32 halves (64B), inner
// 16B-unit u stored at position (u ^ ((m>>1)&3))&3.
__device__ __half g_va[(size_t)M_ * D_];     // 128 MB values fp16
__device__ __half g_wt[(size_t)D_ * D_];     // 2 MB  Ws^T fp16, same block layout (n)
__device__ float g_qpart[KS_ * B_ * D_];
__device__ float g_score[M_];
__device__ float g_ctxpart[NCTX * B_ * D_];

// ---------------- PTX helpers ----------------
__device__ __forceinline__ uint32_t smem_u32(const void* p) {
    uint32_t a;
    asm("{ .reg .u64 t; cvta.to.shared.u64 t, %1; cvt.u32.u64 %0, t; }" : "=r"(a) : "l"(p));
    return a;
}
__device__ __forceinline__ void ldsm4(uint32_t* r, uint32_t addr) {
    asm volatile("ldmatrix.sync.aligned.m8n8.x4.shared.b16 {%0,%1,%2,%3}, [%4];"
        : "=r"(r[0]), "=r"(r[1]), "=r"(r[2]), "=r"(r[3]) : "r"(addr));
}
__device__ __forceinline__ void mma_f32(float* d, const uint32_t* a, uint32_t b0, uint32_t b1) {
    asm("mma.sync.aligned.m16n8k16.row.col.f32.f16.f16.f32 "
        "{%0,%1,%2,%3}, {%4,%5,%6,%7}, {%8,%9}, {%0,%1,%2,%3};"
        : "+f"(d[0]), "+f"(d[1]), "+f"(d[2]), "+f"(d[3])
        : "r"(a[0]), "r"(a[1]), "r"(a[2]), "r"(a[3]), "r"(b0), "r"(b1));
}
#define MBAR_INIT(a, c) \
    asm volatile("mbarrier.init.shared.b64 [%0], %1;" :: "r"((uint32_t)(a)), "r"((uint32_t)(c)) : "memory")
#define MBAR_EXPECT_TX(a, n) \
    asm volatile("mbarrier.arrive.expect_tx.shared.b64 _, [%0], %1;" :: "r"((uint32_t)(a)), "r"((uint32_t)(n)) : "memory")
#define MBAR_WAIT(a, par) do { \
    uint32_t _m = (uint32_t)(a), _p = (uint32_t)(par), _d; \
    asm volatile("{\n\t.reg .pred p;\n\t" \
        "mbarrier.try_wait.parity.acquire.cta.shared::cta.b64 p, [%1], %2;\n\t" \
        "selp.b32 %0, 1, 0, p;\n\t}" : "=r"(_d) : "r"(_m), "r"(_p) : "memory"); \
    if (!_d) { \
        asm volatile("{\n\t.reg .pred P1;\n\t" \
            "WL_%=:\n\t" \
            "mbarrier.try_wait.parity.acquire.cta.shared::cta.b64 P1, [%0], %1, 0x989680;\n\t" \
            "@P1 bra.uni WD_%=;\n\t" \
            "bra.uni WL_%=;\n\t" \
            "WD_%=:\n\t}" :: "r"(_m), "r"(_p) : "memory"); \
    } \
} while (0)
__device__ __forceinline__ void bulk_cp(uint32_t dst, const void* src, uint32_t bytes, uint32_t mbar) {
    asm volatile("cp.async.bulk.shared::cta.global.mbarrier::complete_tx::bytes [%0], [%1], %2, [%3];"
        :: "r"(dst), "l"(src), "r"(bytes), "r"(mbar) : "memory");
}

// ============================================================================
// conv_values: f32 [m][k] -> fp16 chunk-major pre-swizzled g_va
// one thread = one 16B output unit (8 k of one m)
// ============================================================================
__global__ void conv_values_kernel(const float* __restrict__ v) {
    size_t t = (size_t)blockIdx.x * 256 + threadIdx.x;    // 8388608 units
    int u = (int)(t & 3);
    int m = (int)((t >> 2) & (M_ - 1));
    int c = (int)(t >> 18);
    const float4* src = (const float4*)(v + (size_t)m * D_ + c * 32 + u * 8);
    float4 x0 = src[0], x1 = src[1];
    __half h[8];
    h[0] = __float2half_rn(x0.x); h[1] = __float2half_rn(x0.y);
    h[2] = __float2half_rn(x0.z); h[3] = __float2half_rn(x0.w);
    h[4] = __float2half_rn(x1.x); h[5] = __float2half_rn(x1.y);
    h[6] = __float2half_rn(x1.z); h[7] = __float2half_rn(x1.w);
    int sw = (u ^ ((m >> 1) & 3)) & 3;
    *(uint4*)(g_va + ((size_t)c * M_ + m) * 32 + sw * 8) = *(uint4*)h;
}

// ============================================================================
// conv_ws: Ws [k][n] -> transposed fp16 chunk-major pre-swizzled g_wt
// ============================================================================
__global__ void conv_ws_kernel(const float* __restrict__ Ws) {
    __shared__ float tile[32][33];
    const int n0 = blockIdx.x * 32, c = blockIdx.y;       // k0 = c*32
    const int tx = threadIdx.x, ty = threadIdx.y;         // (32, 8)
    #pragma unroll
    for (int i = 0; i < 32; i += 8)
        tile[ty + i][tx] = Ws[(size_t)(c * 32 + ty + i) * D_ + n0 + tx];
    __syncthreads();
    int tid = ty * 32 + tx;
    if (tid < 128) {
        int nl = tid >> 2, u = tid & 3;
        __half h[8];
        #pragma unroll
        for (int j = 0; j < 8; ++j)
            h[j] = __float2half_rn(tile[u * 8 + j][nl]);
        int sw = (u ^ ((nl >> 1) & 3)) & 3;
        *(uint4*)(g_wt + ((size_t)c * D_ + n0 + nl) * 32 + sw * 8) = *(uint4*)h;
    }
}

// ============================================================================
// qproj partials (k-split x4); summed during GEMM epilogue staging
// ============================================================================
__global__ void qproj_part_kernel(const float* __restrict__ query,
                                  const float* __restrict__ Wh,
                                  const float* __restrict__ bh,
                                  const float* __restrict__ bs,
                                  const float* __restrict__ bc) {
    int g  = blockIdx.x * 256 + threadIdx.x;     // 32768
    int ks = blockIdx.y;
    int u = g & (D_ - 1);
    int b = g >> 10;
    float acc = (ks == 0) ? (bh[u] + bs[u] + bc[u]) : 0.0f;
    const float* q = query + (size_t)b * D_;
    int kbeg = ks * (D_ / KS_), kend = kbeg + D_ / KS_;
    #pragma unroll 8
    for (int k = kbeg; k < kend; ++k)
        acc = fmaf(q[k], Wh[(size_t)k * D_ + u], acc);
    g_qpart[(size_t)ks * B_ * D_ + g] = acc;
}

// ============================================================================
// score GEMM: CTA = 128M x 128N subtile (ns=0..7 covers N=1024), 8 warps
// 64x32 each, 2 CTAs/SM. Pure fp16 HMMA, fp32 accumulate.
// smem fill via cp.async.bulk (2 x 8KB per chunk, 1 issuing thread) +
// mbarrier complete_tx; 3-stage pipeline; pre-swizzled gmem blocks.
// ============================================================================
#define BUF_B 16384                 // A 8K | B 8K
#define O_BH  8192
#define NSTAGE 3
#define MBAR_OFF (NSTAGE * BUF_B)   // 49152
#define EPI_OFF (MBAR_OFF + 64)
#define GEMM_SMEM (EPI_OFF + (512 + 512) * 4)   // 53312

__global__ __launch_bounds__(256, 2)
void score_gemm_kernel(const float* __restrict__ prev_cov,
                       const float* __restrict__ Wc,
                       const float* __restrict__ Vw) {
    extern __shared__ char smem[];
    const uint32_t sb = smem_u32(smem);
    float* qb_s = (float*)(smem + EPI_OFF);          // 128
    float* wc_s = qb_s + 128;
    float* vw_s = qb_s + 256;
    float* pc_s = qb_s + 384;                        // 128
    float (*Red)[4] = (float(*)[4])(qb_s + 512);     // [128][4]

    const int tid  = threadIdx.x;
    const int wid  = tid >> 5;
    const int lane = tid & 31;
    const int wm   = (wid >> 2) * 64;                // 0 / 64
    const int wn   = (wid & 3) * 32;                 // 0..96

    const int m0  = blockIdx.x * 128;
    const int b   = blockIdx.x >> 4;
    const int tt0 = (blockIdx.x & 15) * 128;

    if (tid == 0) {
        MBAR_INIT(sb + MBAR_OFF + 0,  1);
        MBAR_INIT(sb + MBAR_OFF + 8,  1);
        MBAR_INIT(sb + MBAR_OFF + 16, 1);
    }
    if (tid < 128) pc_s[tid] = prev_cov[(size_t)b * T_ + tt0 + tid];
    __syncthreads();

    // ---- hoisted fragment addressing (kk=16 differs by ^0x20) ----
    const int lr  = (lane & 7) + (lane & 8);
    const uint32_t k8 = lane >> 4;                   // 0/1
    uint32_t aoff[4], boff[2];
    #pragma unroll
    for (int mf = 0; mf < 4; ++mf) {
        int r = wm + mf * 16 + lr;
        aoff[mf] = (uint32_t)(r << 6) + (((k8 ^ (r >> 1)) & 3) << 4);
    }
    #pragma unroll
    for (int p = 0; p < 2; ++p) {
        int n = wn + p * 16 + lr;
        boff[p] = (uint32_t)(n << 6) + (((k8 ^ (n >> 1)) & 3) << 4) + O_BH;
    }

    float sacc[4][2];
    #pragma unroll
    for (int mf = 0; mf < 4; ++mf) { sacc[mf][0] = 0.f; sacc[mf][1] = 0.f; }

    // one thread issues: expect_tx(16KB) + 2 bulk copies (A block, B block)
    #define ISSUE_BULK(c, ns) do {                                             \
        if (tid == 0) {                                                        \
            int s_ = (c) % NSTAGE;                                             \
            uint32_t mb_ = sb + MBAR_OFF + s_ * 8;                             \
            uint32_t bb_ = sb + s_ * BUF_B;                                    \
            MBAR_EXPECT_TX(mb_, 16384u);                                       \
            bulk_cp(bb_,        g_va + ((size_t)(c) * M_ + m0) * 32,           \
                    8192u, mb_);                                               \
            bulk_cp(bb_ + O_BH, g_wt + ((size_t)(c) * D_ + (ns) * 128) * 32,   \
                    8192u, mb_);                                               \
        }                                                                      \
    } while (0)

    for (int ns = 0; ns < 8; ++ns) {
        // stage epilogue constants for this subtile
        if (tid < 128) {
            int n = ns * 128 + tid;
            float q = g_qpart[(size_t)b * D_ + n]
                    + g_qpart[(size_t)B_ * D_ + (size_t)b * D_ + n]
                    + g_qpart[(size_t)2 * B_ * D_ + (size_t)b * D_ + n]
                    + g_qpart[(size_t)3 * B_ * D_ + (size_t)b * D_ + n];
            qb_s[tid] = q;
            wc_s[tid] = Wc[n];
            vw_s[tid] = Vw[n];
        }

        float acc[4][4][4];
        #pragma unroll
        for (int i = 0; i < 4; ++i)
            #pragma unroll
            for (int j = 0; j < 4; ++j)
                #pragma unroll
                for (int r = 0; r < 4; ++r) acc[i][j][r] = 0.0f;

        ISSUE_BULK(0, ns);
        ISSUE_BULK(1, ns);

        for (int c = 0; c < 32; ++c) {
            const int s = c % NSTAGE;
            // stage-use parity: per-ns uses are 11/11/10 for stages 0/1/2
            const uint32_t par = (uint32_t)((c / 3 + ((s < 2) ? ns : 0)) & 1);
            MBAR_WAIT(sb + MBAR_OFF + s * 8, par);
            __syncthreads();
            if (c + 2 < 32) ISSUE_BULK(c + 2, ns);

            const uint32_t bb = sb + s * BUF_B;
            #pragma unroll
            for (int kk = 0; kk < 32; kk += 16) {
                const uint32_t xm = kk ? 0x20u : 0u;
                uint32_t af[4][4], bf[2][4];
                #pragma unroll
                for (int mf = 0; mf < 4; ++mf) ldsm4(af[mf], (bb + aoff[mf]) ^ xm);
                #pragma unroll
                for (int p = 0; p < 2; ++p) ldsm4(bf[p], (bb + boff[p]) ^ xm);
                #pragma unroll
                for (int mf = 0; mf < 4; ++mf)
                    #pragma unroll
                    for (int p = 0; p < 2; ++p) {
                        mma_f32(acc[mf][2 * p],     af[mf], bf[p][0], bf[p][2]);
                        mma_f32(acc[mf][2 * p + 1], af[mf], bf[p][1], bf[p][3]);
                    }
            }
        }

        // fused epilogue for this subtile
        #pragma unroll
        for (int mf = 0; mf < 4; ++mf) {
            const int rA = wm + mf * 16 + (lane >> 2);
            const float pA = pc_s[rA], pB = pc_s[rA + 8];
            float sA = 0.f, sB = 0.f;
            #pragma unroll
            for (int nf = 0; nf < 4; ++nf) {
                int c0 = wn + nf * 8 + 2 * (lane & 3);
                int c1 = c0 + 1;
                sA += tanhf(acc[mf][nf][0] + qb_s[c0] + pA * wc_s[c0]) * vw_s[c0];
                sA += tanhf(acc[mf][nf][1] + qb_s[c1] + pA * wc_s[c1]) * vw_s[c1];
                sB += tanhf(acc[mf][nf][2] + qb_s[c0] + pB * wc_s[c0]) * vw_s[c0];
                sB += tanhf(acc[mf][nf][3] + qb_s[c1] + pB * wc_s[c1]) * vw_s[c1];
            }
            sacc[mf][0] += sA;
            sacc[mf][1] += sB;
        }
        __syncthreads();   // before next subtile overwrites qb_s/wc_s/vw_s
    }

    // reduce over lanes (n quads) and warps (n-warps), write final scores
    #pragma unroll
    for (int mf = 0; mf < 4; ++mf) {
        float sA = sacc[mf][0], sB = sacc[mf][1];
        sA += __shfl_xor_sync(0xffffffff, sA, 1);
        sA += __shfl_xor_sync(0xffffffff, sA, 2);
        sB += __shfl_xor_sync(0xffffffff, sB, 1);
        sB += __shfl_xor_sync(0xffffffff, sB, 2);
        if ((lane & 3) == 0) {
            int rA = wm + mf * 16 + (lane >> 2);
            Red[rA][wid & 3]     = sA;
            Red[rA + 8][wid & 3] = sB;
        }
    }
    __syncthreads();
    if (tid < 128) {
        g_score[(size_t)m0 + tid] = Red[tid][0] + Red[tid][1] + Red[tid][2] + Red[tid][3];
    }
}

// ============================================================================
// softmax over T per batch; writes attention_weights + coverage
// ============================================================================
__global__ void softmax_kernel(const float* __restrict__ prev_cov,
                               const float* __restrict__ Vb,
                               float* __restrict__ out) {
    __shared__ float sc[T_];
    __shared__ float red[256];
    const int b = blockIdx.x;
    const int tid = threadIdx.x;
    const float vb = Vb[0];

    float lmax = -1e30f;
    for (int t = tid; t < T_; t += 256) {
        float s = g_score[(size_t)b * T_ + t] + vb;
        sc[t] = s;
        lmax = fmaxf(lmax, s);
    }
    red[tid] = lmax;
    __syncthreads();
    for (int st = 128; st > 0; st >>= 1) {
        if (tid < st) red[tid] = fmaxf(red[tid], red[tid + st]);
        __syncthreads();
    }
    const float mx = red[0];
    __syncthreads();

    float lsum = 0.0f;
    for (int t = tid; t < T_; t += 256) {
        float e = expf(sc[t] - mx);
        sc[t] = e;
        lsum += e;
    }
    red[tid] = lsum;
    __syncthreads();
    for (int st = 128; st > 0; st >>= 1) {
        if (tid < st) red[tid] += red[tid + st];
        __syncthreads();
    }
    const float inv = 1.0f / red[0];

    float* aw_out  = out + B_ * D_;
    float* cov_out = out + B_ * D_ + B_ * T_;
    const float* pc = prev_cov + (size_t)b * T_;
    for (int t = tid; t < T_; t += 256) {
        float a = sc[t] * inv;
        aw_out[(size_t)b * T_ + t]  = a;
        cov_out[(size_t)b * T_ + t] = a + pc[t];
    }
}

// ============================================================================
// context partials + reduce
// ============================================================================
__global__ void ctx_part_kernel(const float* __restrict__ values,
                                const float* __restrict__ aw) {
    const int tc = blockIdx.x, b = blockIdx.y, tid = threadIdx.x;
    __shared__ float sa[128];
    const int t0 = tc * 128;
    if (tid < 128) sa[tid] = aw[(size_t)b * T_ + t0 + tid];
    __syncthreads();

    const float4* vp = (const float4*)(values) + ((size_t)b * T_ + t0) * (D_ / 4) + tid;
    float4 acc = make_float4(0.f, 0.f, 0.f, 0.f);
    #pragma unroll 4
    for (int t = 0; t < 128; ++t) {
        float4 v = vp[(size_t)t * (D_ / 4)];
        float a = sa[t];
        acc.x = fmaf(a, v.x, acc.x);
        acc.y = fmaf(a, v.y, acc.y);
        acc.z = fmaf(a, v.z, acc.z);
        acc.w = fmaf(a, v.w, acc.w);
    }
    ((float4*)g_ctxpart)[((size_t)tc * B_ + b) * (D_ / 4) + tid] = acc;
}

__global__ void ctx_reduce_kernel(float* __restrict__ out) {
    int g = blockIdx.x * blockDim.x + threadIdx.x;
    float s = 0.0f;
    #pragma unroll
    for (int tc = 0; tc < NCTX; ++tc)
        s += g_ctxpart[(size_t)tc * B_ * D_ + g];
    out[g] = s;
}

// ============================================================================
extern "C" void kernel_launch(void* const* d_in, const int* in_sizes, int n_in,
                              void* d_out, int out_size) {
    const float* query    = (const float*)d_in[0];
    const float* values   = (const float*)d_in[1];
    const float* prev_cov = (const float*)d_in[2];
    const float* Wh       = (const float*)d_in[3];
    const float* bh       = (const float*)d_in[4];
    const float* Ws       = (const float*)d_in[5];
    const float* bs       = (const float*)d_in[6];
    const float* Wc       = (const float*)d_in[7];
    const float* bc       = (const float*)d_in[8];
    const float* Vw       = (const float*)d_in[9];
    const float* Vb       = (const float*)d_in[10];
    float* out = (float*)d_out;

    cudaFuncSetAttribute(score_gemm_kernel,
                         cudaFuncAttributeMaxDynamicSharedMemorySize, GEMM_SMEM);

    conv_values_kernel<<<32768, 256>>>(values);
    conv_ws_kernel<<<dim3(32, 32), dim3(32, 8)>>>(Ws);
    qproj_part_kernel<<<dim3(128, KS_), 256>>>(query, Wh, bh, bs, bc);
    score_gemm_kernel<<<M_ / 128, 256, GEMM_SMEM>>>(prev_cov, Wc, Vw);
    softmax_kernel<<<B_, 256>>>(prev_cov, Vb, out);
    ctx_part_kernel<<<dim3(NCTX, B_), 256>>>(values, out + B_ * D_);
    ctx_reduce_kernel<<<(B_ * D_) / 256, 256>>>(out);
}

// round 13
// speedup vs baseline: 2.7840x; 1.0590x over previous
#include <cuda_runtime.h>
#include <cuda_fp16.h>
#include <math.h>
#include <stdint.h>

#define B_  32
#define T_  2048
#define D_  1024
#define M_  (B_ * T_)
#define NCTX 16
#define KS_  4

// ---------------- scratch (static device globals; no allocation) ----------------
// chunk-major, pre-swizzled: block (c, m) at (c*M_ + m)*32 halves (64B), inner
// 16B-unit u stored at position (u ^ ((m>>1)&3))&3.
__device__ __half g_va[(size_t)M_ * D_];     // 128 MB values fp16
__device__ __half g_wt[(size_t)D_ * D_];     // 2 MB  Ws^T fp16, same block layout (n)
__device__ float g_qpart[KS_ * B_ * D_];
__device__ float g_spart[4 * M_];            // per-n-quarter score partials
__device__ float g_ctxpart[NCTX * B_ * D_];

// ---------------- PTX helpers ----------------
__device__ __forceinline__ uint32_t smem_u32(const void* p) {
    uint32_t a;
    asm("{ .reg .u64 t; cvta.to.shared.u64 t, %1; cvt.u32.u64 %0, t; }" : "=r"(a) : "l"(p));
    return a;
}
__device__ __forceinline__ void ldsm4(uint32_t* r, uint32_t addr) {
    asm volatile("ldmatrix.sync.aligned.m8n8.x4.shared.b16 {%0,%1,%2,%3}, [%4];"
        : "=r"(r[0]), "=r"(r[1]), "=r"(r[2]), "=r"(r[3]) : "r"(addr));
}
__device__ __forceinline__ void mma_f32(float* d, const uint32_t* a, uint32_t b0, uint32_t b1) {
    asm("mma.sync.aligned.m16n8k16.row.col.f32.f16.f16.f32 "
        "{%0,%1,%2,%3}, {%4,%5,%6,%7}, {%8,%9}, {%0,%1,%2,%3};"
        : "+f"(d[0]), "+f"(d[1]), "+f"(d[2]), "+f"(d[3])
        : "r"(a[0]), "r"(a[1]), "r"(a[2]), "r"(a[3]), "r"(b0), "r"(b1));
}
#define MBAR_INIT(a, c) \
    asm volatile("mbarrier.init.shared.b64 [%0], %1;" :: "r"((uint32_t)(a)), "r"((uint32_t)(c)) : "memory")
#define MBAR_EXPECT_TX(a, n) \
    asm volatile("mbarrier.arrive.expect_tx.shared.b64 _, [%0], %1;" :: "r"((uint32_t)(a)), "r"((uint32_t)(n)) : "memory")
#define MBAR_WAIT(a, par) do { \
    uint32_t _m = (uint32_t)(a), _p = (uint32_t)(par), _d; \
    asm volatile("{\n\t.reg .pred p;\n\t" \
        "mbarrier.try_wait.parity.acquire.cta.shared::cta.b64 p, [%1], %2;\n\t" \
        "selp.b32 %0, 1, 0, p;\n\t}" : "=r"(_d) : "r"(_m), "r"(_p) : "memory"); \
    if (!_d) { \
        asm volatile("{\n\t.reg .pred P1;\n\t" \
            "WL_%=:\n\t" \
            "mbarrier.try_wait.parity.acquire.cta.shared::cta.b64 P1, [%0], %1, 0x989680;\n\t" \
            "@P1 bra.uni WD_%=;\n\t" \
            "bra.uni WL_%=;\n\t" \
            "WD_%=:\n\t}" :: "r"(_m), "r"(_p) : "memory"); \
    } \
} while (0)
__device__ __forceinline__ void bulk_cp(uint32_t dst, const void* src, uint32_t bytes, uint32_t mbar) {
    asm volatile("cp.async.bulk.shared::cta.global.mbarrier::complete_tx::bytes [%0], [%1], %2, [%3];"
        :: "r"(dst), "l"(src), "r"(bytes), "r"(mbar) : "memory");
}

// ============================================================================
// conv_values: f32 [m][k] -> fp16 chunk-major pre-swizzled g_va
// ============================================================================
__global__ void conv_values_kernel(const float* __restrict__ v) {
    size_t t = (size_t)blockIdx.x * 256 + threadIdx.x;    // 8388608 units
    int u = (int)(t & 3);
    int m = (int)((t >> 2) & (M_ - 1));
    int c = (int)(t >> 18);
    const float4* src = (const float4*)(v + (size_t)m * D_ + c * 32 + u * 8);
    float4 x0 = src[0], x1 = src[1];
    __half h[8];
    h[0] = __float2half_rn(x0.x); h[1] = __float2half_rn(x0.y);
    h[2] = __float2half_rn(x0.z); h[3] = __float2half_rn(x0.w);
    h[4] = __float2half_rn(x1.x); h[5] = __float2half_rn(x1.y);
    h[6] = __float2half_rn(x1.z); h[7] = __float2half_rn(x1.w);
    int sw = (u ^ ((m >> 1) & 3)) & 3;
    *(uint4*)(g_va + ((size_t)c * M_ + m) * 32 + sw * 8) = *(uint4*)h;
}

// ============================================================================
// conv_ws: Ws [k][n] -> transposed fp16 chunk-major pre-swizzled g_wt
// ============================================================================
__global__ void conv_ws_kernel(const float* __restrict__ Ws) {
    __shared__ float tile[32][33];
    const int n0 = blockIdx.x * 32, c = blockIdx.y;       // k0 = c*32
    const int tx = threadIdx.x, ty = threadIdx.y;         // (32, 8)
    #pragma unroll
    for (int i = 0; i < 32; i += 8)
        tile[ty + i][tx] = Ws[(size_t)(c * 32 + ty + i) * D_ + n0 + tx];
    __syncthreads();
    int tid = ty * 32 + tx;
    if (tid < 128) {
        int nl = tid >> 2, u = tid & 3;
        __half h[8];
        #pragma unroll
        for (int j = 0; j < 8; ++j)
            h[j] = __float2half_rn(tile[u * 8 + j][nl]);
        int sw = (u ^ ((nl >> 1) & 3)) & 3;
        *(uint4*)(g_wt + ((size_t)c * D_ + n0 + nl) * 32 + sw * 8) = *(uint4*)h;
    }
}

// ============================================================================
// qproj partials (k-split x4); summed during GEMM epilogue staging
// ============================================================================
__global__ void qproj_part_kernel(const float* __restrict__ query,
                                  const float* __restrict__ Wh,
                                  const float* __restrict__ bh,
                                  const float* __restrict__ bs,
                                  const float* __restrict__ bc) {
    int g  = blockIdx.x * 256 + threadIdx.x;     // 32768
    int ks = blockIdx.y;
    int u = g & (D_ - 1);
    int b = g >> 10;
    float acc = (ks == 0) ? (bh[u] + bs[u] + bc[u]) : 0.0f;
    const float* q = query + (size_t)b * D_;
    int kbeg = ks * (D_ / KS_), kend = kbeg + D_ / KS_;
    #pragma unroll 8
    for (int k = kbeg; k < kend; ++k)
        acc = fmaf(q[k], Wh[(size_t)k * D_ + u], acc);
    g_qpart[(size_t)ks * B_ * D_ + g] = acc;
}

// ============================================================================
// score GEMM: CTA = 128M x 256N quarter; grid (512 m-blocks, 4 n-quarters).
// 8 warps, warp tile 64x64 (A and B fragments each reused 4x -> LDSM
// bytes/MMA = 128, ~50% smem crossbar). Pure fp16 HMMA, fp32 accumulate.
// smem fill via cp.async.bulk (A 8KB + B 16KB per chunk) + mbarrier.
// ============================================================================
#define BUF_B 24576                 // A 8K | B 16K
#define O_BH  8192
#define NSTAGE 3
#define MBAR_OFF (NSTAGE * BUF_B)   // 73728
#define EPI_OFF (MBAR_OFF + 64)
#define GEMM_SMEM (EPI_OFF + (256 * 3 + 128 + 512) * 4)   // +5632

__global__ __launch_bounds__(256, 1)
void score_gemm_kernel(const float* __restrict__ prev_cov,
                       const float* __restrict__ Wc,
                       const float* __restrict__ Vw) {
    extern __shared__ char smem[];
    const uint32_t sb = smem_u32(smem);
    float* qb_s = (float*)(smem + EPI_OFF);          // 256
    float* wc_s = qb_s + 256;
    float* vw_s = qb_s + 512;
    float* pc_s = qb_s + 768;                        // 128
    float (*Red)[4] = (float(*)[4])(qb_s + 896);     // [128][4]

    const int tid  = threadIdx.x;
    const int wid  = tid >> 5;
    const int lane = tid & 31;
    const int wm   = (wid >> 2) * 64;                // 0 / 64
    const int wn   = (wid & 3) * 64;                 // 0..192

    const int mb  = blockIdx.x;                      // 0..511
    const int nh  = blockIdx.y;                      // 0..3
    const int m0  = mb * 128;
    const int b   = mb >> 4;
    const int tt0 = (mb & 15) * 128;

    if (tid == 0) {
        MBAR_INIT(sb + MBAR_OFF + 0,  1);
        MBAR_INIT(sb + MBAR_OFF + 8,  1);
        MBAR_INIT(sb + MBAR_OFF + 16, 1);
    }
    if (tid < 128) pc_s[tid] = prev_cov[(size_t)b * T_ + tt0 + tid];
    // epilogue constants for this n-quarter
    {
        int n = nh * 256 + tid;
        float q = g_qpart[(size_t)b * D_ + n]
                + g_qpart[(size_t)B_ * D_ + (size_t)b * D_ + n]
                + g_qpart[(size_t)2 * B_ * D_ + (size_t)b * D_ + n]
                + g_qpart[(size_t)3 * B_ * D_ + (size_t)b * D_ + n];
        qb_s[tid] = q;
        wc_s[tid] = Wc[n];
        vw_s[tid] = Vw[n];
    }
    __syncthreads();

    // ---- hoisted fragment addressing (kk=16 differs by ^0x20) ----
    const int lr  = (lane & 7) + (lane & 8);
    const uint32_t k8 = lane >> 4;                   // 0/1
    uint32_t aoff[4], boff[4];
    #pragma unroll
    for (int mf = 0; mf < 4; ++mf) {
        int r = wm + mf * 16 + lr;
        aoff[mf] = (uint32_t)(r << 6) + (((k8 ^ (r >> 1)) & 3) << 4);
    }
    #pragma unroll
    for (int p = 0; p < 4; ++p) {
        int n = wn + p * 16 + lr;
        boff[p] = (uint32_t)(n << 6) + (((k8 ^ (n >> 1)) & 3) << 4) + O_BH;
    }

    float acc[4][8][4];
    #pragma unroll
    for (int i = 0; i < 4; ++i)
        #pragma unroll
        for (int j = 0; j < 8; ++j)
            #pragma unroll
            for (int r = 0; r < 4; ++r) acc[i][j][r] = 0.0f;

    // one thread issues: expect_tx(24KB) + A bulk (8KB) + B bulk (16KB)
    #define ISSUE_BULK(c) do {                                                 \
        if (tid == 0) {                                                        \
            int s_ = (c) % NSTAGE;                                             \
            uint32_t mb_ = sb + MBAR_OFF + s_ * 8;                             \
            uint32_t bb_ = sb + s_ * BUF_B;                                    \
            MBAR_EXPECT_TX(mb_, 24576u);                                       \
            bulk_cp(bb_,        g_va + ((size_t)(c) * M_ + m0) * 32,           \
                    8192u, mb_);                                               \
            bulk_cp(bb_ + O_BH, g_wt + ((size_t)(c) * D_ + nh * 256) * 32,     \
                    16384u, mb_);                                              \
        }                                                                      \
    } while (0)

    ISSUE_BULK(0);
    ISSUE_BULK(1);

    for (int c = 0; c < 32; ++c) {
        const int s = c % NSTAGE;
        MBAR_WAIT(sb + MBAR_OFF + s * 8, (uint32_t)((c / 3) & 1));
        __syncthreads();
        if (c + 2 < 32) ISSUE_BULK(c + 2);

        const uint32_t bb = sb + s * BUF_B;
        #pragma unroll
        for (int kk = 0; kk < 32; kk += 16) {
            const uint32_t xm = kk ? 0x20u : 0u;
            uint32_t af[4][4], bf[4][4];
            #pragma unroll
            for (int mf = 0; mf < 4; ++mf) ldsm4(af[mf], (bb + aoff[mf]) ^ xm);
            #pragma unroll
            for (int p = 0; p < 4; ++p)   ldsm4(bf[p], (bb + boff[p]) ^ xm);
            #pragma unroll
            for (int mf = 0; mf < 4; ++mf)
                #pragma unroll
                for (int p = 0; p < 4; ++p) {
                    mma_f32(acc[mf][2 * p],     af[mf], bf[p][0], bf[p][2]);
                    mma_f32(acc[mf][2 * p + 1], af[mf], bf[p][1], bf[p][3]);
                }
        }
    }

    // fused epilogue: tanh(act + qb + pc*Wc) * Vw, reduce over this n-quarter
    #pragma unroll
    for (int mf = 0; mf < 4; ++mf) {
        const int rA = wm + mf * 16 + (lane >> 2);
        const float pA = pc_s[rA], pB = pc_s[rA + 8];
        float sA = 0.f, sB = 0.f;
        #pragma unroll
        for (int nf = 0; nf < 8; ++nf) {
            int c0 = wn + nf * 8 + 2 * (lane & 3);
            int c1 = c0 + 1;
            sA += tanhf(acc[mf][nf][0] + qb_s[c0] + pA * wc_s[c0]) * vw_s[c0];
            sA += tanhf(acc[mf][nf][1] + qb_s[c1] + pA * wc_s[c1]) * vw_s[c1];
            sB += tanhf(acc[mf][nf][2] + qb_s[c0] + pB * wc_s[c0]) * vw_s[c0];
            sB += tanhf(acc[mf][nf][3] + qb_s[c1] + pB * wc_s[c1]) * vw_s[c1];
        }
        sA += __shfl_xor_sync(0xffffffff, sA, 1);
        sA += __shfl_xor_sync(0xffffffff, sA, 2);
        sB += __shfl_xor_sync(0xffffffff, sB, 1);
        sB += __shfl_xor_sync(0xffffffff, sB, 2);
        if ((lane & 3) == 0) {
            Red[rA][wid & 3]     = sA;
            Red[rA + 8][wid & 3] = sB;
        }
    }
    __syncthreads();
    if (tid < 128) {
        g_spart[(size_t)nh * M_ + m0 + tid] =
            Red[tid][0] + Red[tid][1] + Red[tid][2] + Red[tid][3];
    }
}

// ============================================================================
// softmax over T per batch; writes attention_weights + coverage
// ============================================================================
__global__ void softmax_kernel(const float* __restrict__ prev_cov,
                               const float* __restrict__ Vb,
                               float* __restrict__ out) {
    __shared__ float sc[T_];
    __shared__ float red[256];
    const int b = blockIdx.x;
    const int tid = threadIdx.x;
    const float vb = Vb[0];

    float lmax = -1e30f;
    for (int t = tid; t < T_; t += 256) {
        size_t i = (size_t)b * T_ + t;
        float s = g_spart[i] + g_spart[M_ + i] + g_spart[2 * (size_t)M_ + i]
                + g_spart[3 * (size_t)M_ + i] + vb;
        sc[t] = s;
        lmax = fmaxf(lmax, s);
    }
    red[tid] = lmax;
    __syncthreads();
    for (int st = 128; st > 0; st >>= 1) {
        if (tid < st) red[tid] = fmaxf(red[tid], red[tid + st]);
        __syncthreads();
    }
    const float mx = red[0];
    __syncthreads();

    float lsum = 0.0f;
    for (int t = tid; t < T_; t += 256) {
        float e = expf(sc[t] - mx);
        sc[t] = e;
        lsum += e;
    }
    red[tid] = lsum;
    __syncthreads();
    for (int st = 128; st > 0; st >>= 1) {
        if (tid < st) red[tid] += red[tid + st];
        __syncthreads();
    }
    const float inv = 1.0f / red[0];

    float* aw_out  = out + B_ * D_;
    float* cov_out = out + B_ * D_ + B_ * T_;
    const float* pc = prev_cov + (size_t)b * T_;
    for (int t = tid; t < T_; t += 256) {
        float a = sc[t] * inv;
        aw_out[(size_t)b * T_ + t]  = a;
        cov_out[(size_t)b * T_ + t] = a + pc[t];
    }
}

// ============================================================================
// context partials + reduce
// ============================================================================
__global__ void ctx_part_kernel(const float* __restrict__ values,
                                const float* __restrict__ aw) {
    const int tc = blockIdx.x, b = blockIdx.y, tid = threadIdx.x;
    __shared__ float sa[128];
    const int t0 = tc * 128;
    if (tid < 128) sa[tid] = aw[(size_t)b * T_ + t0 + tid];
    __syncthreads();

    const float4* vp = (const float4*)(values) + ((size_t)b * T_ + t0) * (D_ / 4) + tid;
    float4 acc = make_float4(0.f, 0.f, 0.f, 0.f);
    #pragma unroll 4
    for (int t = 0; t < 128; ++t) {
        float4 v = vp[(size_t)t * (D_ / 4)];
        float a = sa[t];
        acc.x = fmaf(a, v.x, acc.x);
        acc.y = fmaf(a, v.y, acc.y);
        acc.z = fmaf(a, v.z, acc.z);
        acc.w = fmaf(a, v.w, acc.w);
    }
    ((float4*)g_ctxpart)[((size_t)tc * B_ + b) * (D_ / 4) + tid] = acc;
}

__global__ void ctx_reduce_kernel(float* __restrict__ out) {
    int g = blockIdx.x * blockDim.x + threadIdx.x;
    float s = 0.0f;
    #pragma unroll
    for (int tc = 0; tc < NCTX; ++tc)
        s += g_ctxpart[(size_t)tc * B_ * D_ + g];
    out[g] = s;
}

// ============================================================================
extern "C" void kernel_launch(void* const* d_in, const int* in_sizes, int n_in,
                              void* d_out, int out_size) {
    const float* query    = (const float*)d_in[0];
    const float* values   = (const float*)d_in[1];
    const float* prev_cov = (const float*)d_in[2];
    const float* Wh       = (const float*)d_in[3];
    const float* bh       = (const float*)d_in[4];
    const float* Ws       = (const float*)d_in[5];
    const float* bs       = (const float*)d_in[6];
    const float* Wc       = (const float*)d_in[7];
    const float* bc       = (const float*)d_in[8];
    const float* Vw       = (const float*)d_in[9];
    const float* Vb       = (const float*)d_in[10];
    float* out = (float*)d_out;

    cudaFuncSetAttribute(score_gemm_kernel,
                         cudaFuncAttributeMaxDynamicSharedMemorySize, GEMM_SMEM);

    conv_values_kernel<<<32768, 256>>>(values);
    conv_ws_kernel<<<dim3(32, 32), dim3(32, 8)>>>(Ws);
    qproj_part_kernel<<<dim3(128, KS_), 256>>>(query, Wh, bh, bs, bc);
    score_gemm_kernel<<<dim3(M_ / 128, 4), 256, GEMM_SMEM>>>(prev_cov, Wc, Vw);
    softmax_kernel<<<B_, 256>>>(prev_cov, Vb, out);
    ctx_part_kernel<<<dim3(NCTX, B_), 256>>>(values, out + B_ * D_);
    ctx_reduce_kernel<<<(B_ * D_) / 256, 256>>>(out);
}

// round 14
// speedup vs baseline: 2.8257x; 1.0150x over previous
#include <cuda_runtime.h>
#include <cuda_fp16.h>
#include <math.h>
#include <stdint.h>

#define B_  32
#define T_  2048
#define D_  1024
#define M_  (B_ * T_)
#define NCTXP 32            // ctx partials: 16 t-chunks x 2 parity halves
#define KS_  4

// ---------------- scratch (static device globals; no allocation) ----------------
// chunk-major, pre-swizzled: block (c, m) at (c*M_ + m)*32 halves (64B), inner
// 16B-unit u stored at position (u ^ ((m>>1)&3))&3.
__device__ __half g_va[(size_t)M_ * D_];     // 128 MB values fp16
__device__ __half g_wt[(size_t)D_ * D_];     // 2 MB  Ws^T fp16, same block layout (n)
__device__ float g_qpart[KS_ * B_ * D_];
__device__ float g_spart[4 * M_];            // per-n-quarter score partials
__device__ float g_ctxpart[NCTXP * B_ * D_];

// ---------------- PTX helpers ----------------
__device__ __forceinline__ uint32_t smem_u32(const void* p) {
    uint32_t a;
    asm("{ .reg .u64 t; cvta.to.shared.u64 t, %1; cvt.u32.u64 %0, t; }" : "=r"(a) : "l"(p));
    return a;
}
__device__ __forceinline__ void ldsm4(uint32_t* r, uint32_t addr) {
    asm volatile("ldmatrix.sync.aligned.m8n8.x4.shared.b16 {%0,%1,%2,%3}, [%4];"
        : "=r"(r[0]), "=r"(r[1]), "=r"(r[2]), "=r"(r[3]) : "r"(addr));
}
__device__ __forceinline__ void mma_f32(float* d, const uint32_t* a, uint32_t b0, uint32_t b1) {
    asm("mma.sync.aligned.m16n8k16.row.col.f32.f16.f16.f32 "
        "{%0,%1,%2,%3}, {%4,%5,%6,%7}, {%8,%9}, {%0,%1,%2,%3};"
        : "+f"(d[0]), "+f"(d[1]), "+f"(d[2]), "+f"(d[3])
        : "r"(a[0]), "r"(a[1]), "r"(a[2]), "r"(a[3]), "r"(b0), "r"(b1));
}
#define MBAR_INIT(a, c) \
    asm volatile("mbarrier.init.shared.b64 [%0], %1;" :: "r"((uint32_t)(a)), "r"((uint32_t)(c)) : "memory")
#define MBAR_EXPECT_TX(a, n) \
    asm volatile("mbarrier.arrive.expect_tx.shared.b64 _, [%0], %1;" :: "r"((uint32_t)(a)), "r"((uint32_t)(n)) : "memory")
#define MBAR_WAIT(a, par) do { \
    uint32_t _m = (uint32_t)(a), _p = (uint32_t)(par), _d; \
    asm volatile("{\n\t.reg .pred p;\n\t" \
        "mbarrier.try_wait.parity.acquire.cta.shared::cta.b64 p, [%1], %2;\n\t" \
        "selp.b32 %0, 1, 0, p;\n\t}" : "=r"(_d) : "r"(_m), "r"(_p) : "memory"); \
    if (!_d) { \
        asm volatile("{\n\t.reg .pred P1;\n\t" \
            "WL_%=:\n\t" \
            "mbarrier.try_wait.parity.acquire.cta.shared::cta.b64 P1, [%0], %1, 0x989680;\n\t" \
            "@P1 bra.uni WD_%=;\n\t" \
            "bra.uni WL_%=;\n\t" \
            "WD_%=:\n\t}" :: "r"(_m), "r"(_p) : "memory"); \
    } \
} while (0)
__device__ __forceinline__ void bulk_cp(uint32_t dst, const void* src, uint32_t bytes, uint32_t mbar) {
    asm volatile("cp.async.bulk.shared::cta.global.mbarrier::complete_tx::bytes [%0], [%1], %2, [%3];"
        :: "r"(dst), "l"(src), "r"(bytes), "r"(mbar) : "memory");
}

// ============================================================================
// merged prep: conv_values (32768 blocks) | conv_ws (1024) | qproj (512)
// ============================================================================
#define NB_CV 32768
#define NB_CW 1024
#define NB_QP 512
__global__ void prep_kernel(const float* __restrict__ v,
                            const float* __restrict__ Ws,
                            const float* __restrict__ query,
                            const float* __restrict__ Wh,
                            const float* __restrict__ bh,
                            const float* __restrict__ bs,
                            const float* __restrict__ bc) {
    __shared__ float tile[32][33];
    const int bid = blockIdx.x;
    const int tid = threadIdx.x;

    if (bid < NB_CV) {
        // ---- conv_values: f32 [m][k] -> fp16 chunk-major pre-swizzled ----
        size_t t = (size_t)bid * 256 + tid;
        int u = (int)(t & 3);
        int m = (int)((t >> 2) & (M_ - 1));
        int c = (int)(t >> 18);
        const float4* src = (const float4*)(v + (size_t)m * D_ + c * 32 + u * 8);
        float4 x0 = src[0], x1 = src[1];
        __half h[8];
        h[0] = __float2half_rn(x0.x); h[1] = __float2half_rn(x0.y);
        h[2] = __float2half_rn(x0.z); h[3] = __float2half_rn(x0.w);
        h[4] = __float2half_rn(x1.x); h[5] = __float2half_rn(x1.y);
        h[6] = __float2half_rn(x1.z); h[7] = __float2half_rn(x1.w);
        int sw = (u ^ ((m >> 1) & 3)) & 3;
        *(uint4*)(g_va + ((size_t)c * M_ + m) * 32 + sw * 8) = *(uint4*)h;
    } else if (bid < NB_CV + NB_CW) {
        // ---- conv_ws: Ws [k][n] -> transposed fp16 chunk-major swizzled ----
        int cw = bid - NB_CV;
        const int n0 = (cw & 31) * 32, c = cw >> 5;
        const int tx = tid & 31, ty = tid >> 5;
        #pragma unroll
        for (int i = 0; i < 32; i += 8)
            tile[ty + i][tx] = Ws[(size_t)(c * 32 + ty + i) * D_ + n0 + tx];
        __syncthreads();
        if (tid < 128) {
            int nl = tid >> 2, u = tid & 3;
            __half h[8];
            #pragma unroll
            for (int j = 0; j < 8; ++j)
                h[j] = __float2half_rn(tile[u * 8 + j][nl]);
            int sw = (u ^ ((nl >> 1) & 3)) & 3;
            *(uint4*)(g_wt + ((size_t)c * D_ + n0 + nl) * 32 + sw * 8) = *(uint4*)h;
        }
    } else {
        // ---- qproj partials (k-split x4) ----
        int kbid = bid - NB_CV - NB_CW;
        int ks = kbid >> 7;
        int g  = (kbid & 127) * 256 + tid;
        int u = g & (D_ - 1);
        int b = g >> 10;
        float acc = (ks == 0) ? (bh[u] + bs[u] + bc[u]) : 0.0f;
        const float* q = query + (size_t)b * D_;
        int kbeg = ks * (D_ / KS_), kend = kbeg + D_ / KS_;
        #pragma unroll 8
        for (int k = kbeg; k < kend; ++k)
            acc = fmaf(q[k], Wh[(size_t)k * D_ + u], acc);
        g_qpart[(size_t)ks * B_ * D_ + g] = acc;
    }
}

// ============================================================================
// score GEMM: CTA = 128M x 256N quarter; grid (4 n-quarters, 512 m-blocks)
// (x-fastest dispatch => 4 quarters of one m-block adjacent -> A L2 reuse).
// 8 warps, warp tile 64x64. Pure fp16 HMMA, fp32 accumulate.
// smem fill via cp.async.bulk (A 8KB + B 16KB per chunk) + mbarrier.
// ============================================================================
#define BUF_B 24576                 // A 8K | B 16K
#define O_BH  8192
#define NSTAGE 3
#define MBAR_OFF (NSTAGE * BUF_B)   // 73728
#define EPI_OFF (MBAR_OFF + 64)
#define GEMM_SMEM (EPI_OFF + (256 * 3 + 128 + 512) * 4)

__global__ __launch_bounds__(256, 1)
void score_gemm_kernel(const float* __restrict__ prev_cov,
                       const float* __restrict__ Wc,
                       const float* __restrict__ Vw) {
    extern __shared__ char smem[];
    const uint32_t sb = smem_u32(smem);
    float* qb_s = (float*)(smem + EPI_OFF);          // 256
    float* wc_s = qb_s + 256;
    float* vw_s = qb_s + 512;
    float* pc_s = qb_s + 768;                        // 128
    float (*Red)[4] = (float(*)[4])(qb_s + 896);     // [128][4]

    const int tid  = threadIdx.x;
    const int wid  = tid >> 5;
    const int lane = tid & 31;
    const int wm   = (wid >> 2) * 64;                // 0 / 64
    const int wn   = (wid & 3) * 64;                 // 0..192

    const int nh  = blockIdx.x;                      // 0..3
    const int mb  = blockIdx.y;                      // 0..511
    const int m0  = mb * 128;
    const int b   = mb >> 4;
    const int tt0 = (mb & 15) * 128;

    if (tid == 0) {
        MBAR_INIT(sb + MBAR_OFF + 0,  1);
        MBAR_INIT(sb + MBAR_OFF + 8,  1);
        MBAR_INIT(sb + MBAR_OFF + 16, 1);
    }
    if (tid < 128) pc_s[tid] = prev_cov[(size_t)b * T_ + tt0 + tid];
    {
        int n = nh * 256 + tid;
        float q = g_qpart[(size_t)b * D_ + n]
                + g_qpart[(size_t)B_ * D_ + (size_t)b * D_ + n]
                + g_qpart[(size_t)2 * B_ * D_ + (size_t)b * D_ + n]
                + g_qpart[(size_t)3 * B_ * D_ + (size_t)b * D_ + n];
        qb_s[tid] = q;
        wc_s[tid] = Wc[n];
        vw_s[tid] = Vw[n];
    }
    __syncthreads();

    // ---- hoisted fragment addressing (kk=16 differs by ^0x20) ----
    const int lr  = (lane & 7) + (lane & 8);
    const uint32_t k8 = lane >> 4;                   // 0/1
    uint32_t aoff[4], boff[4];
    #pragma unroll
    for (int mf = 0; mf < 4; ++mf) {
        int r = wm + mf * 16 + lr;
        aoff[mf] = (uint32_t)(r << 6) + (((k8 ^ (r >> 1)) & 3) << 4);
    }
    #pragma unroll
    for (int p = 0; p < 4; ++p) {
        int n = wn + p * 16 + lr;
        boff[p] = (uint32_t)(n << 6) + (((k8 ^ (n >> 1)) & 3) << 4) + O_BH;
    }

    float acc[4][8][4];
    #pragma unroll
    for (int i = 0; i < 4; ++i)
        #pragma unroll
        for (int j = 0; j < 8; ++j)
            #pragma unroll
            for (int r = 0; r < 4; ++r) acc[i][j][r] = 0.0f;

    #define ISSUE_BULK(c) do {                                                 \
        if (tid == 0) {                                                        \
            int s_ = (c) % NSTAGE;                                             \
            uint32_t mb_ = sb + MBAR_OFF + s_ * 8;                             \
            uint32_t bb_ = sb + s_ * BUF_B;                                    \
            MBAR_EXPECT_TX(mb_, 24576u);                                       \
            bulk_cp(bb_,        g_va + ((size_t)(c) * M_ + m0) * 32,           \
                    8192u, mb_);                                               \
            bulk_cp(bb_ + O_BH, g_wt + ((size_t)(c) * D_ + nh * 256) * 32,     \
                    16384u, mb_);                                              \
        }                                                                      \
    } while (0)

    ISSUE_BULK(0);
    ISSUE_BULK(1);

    for (int c = 0; c < 32; ++c) {
        const int s = c % NSTAGE;
        MBAR_WAIT(sb + MBAR_OFF + s * 8, (uint32_t)((c / 3) & 1));
        __syncthreads();
        if (c + 2 < 32) ISSUE_BULK(c + 2);

        const uint32_t bb = sb + s * BUF_B;
        #pragma unroll
        for (int kk = 0; kk < 32; kk += 16) {
            const uint32_t xm = kk ? 0x20u : 0u;
            uint32_t af[4][4], bf[4][4];
            #pragma unroll
            for (int mf = 0; mf < 4; ++mf) ldsm4(af[mf], (bb + aoff[mf]) ^ xm);
            #pragma unroll
            for (int p = 0; p < 4; ++p)   ldsm4(bf[p], (bb + boff[p]) ^ xm);
            #pragma unroll
            for (int mf = 0; mf < 4; ++mf)
                #pragma unroll
                for (int p = 0; p < 4; ++p) {
                    mma_f32(acc[mf][2 * p],     af[mf], bf[p][0], bf[p][2]);
                    mma_f32(acc[mf][2 * p + 1], af[mf], bf[p][1], bf[p][3]);
                }
        }
    }

    // fused epilogue: tanh(act + qb + pc*Wc) * Vw, reduce over this n-quarter
    #pragma unroll
    for (int mf = 0; mf < 4; ++mf) {
        const int rA = wm + mf * 16 + (lane >> 2);
        const float pA = pc_s[rA], pB = pc_s[rA + 8];
        float sA = 0.f, sB = 0.f;
        #pragma unroll
        for (int nf = 0; nf < 8; ++nf) {
            int c0 = wn + nf * 8 + 2 * (lane & 3);
            int c1 = c0 + 1;
            sA += tanhf(acc[mf][nf][0] + qb_s[c0] + pA * wc_s[c0]) * vw_s[c0];
            sA += tanhf(acc[mf][nf][1] + qb_s[c1] + pA * wc_s[c1]) * vw_s[c1];
            sB += tanhf(acc[mf][nf][2] + qb_s[c0] + pB * wc_s[c0]) * vw_s[c0];
            sB += tanhf(acc[mf][nf][3] + qb_s[c1] + pB * wc_s[c1]) * vw_s[c1];
        }
        sA += __shfl_xor_sync(0xffffffff, sA, 1);
        sA += __shfl_xor_sync(0xffffffff, sA, 2);
        sB += __shfl_xor_sync(0xffffffff, sB, 1);
        sB += __shfl_xor_sync(0xffffffff, sB, 2);
        if ((lane & 3) == 0) {
            Red[rA][wid & 3]     = sA;
            Red[rA + 8][wid & 3] = sB;
        }
    }
    __syncthreads();
    if (tid < 128) {
        g_spart[(size_t)nh * M_ + m0 + tid] =
            Red[tid][0] + Red[tid][1] + Red[tid][2] + Red[tid][3];
    }
}

// ============================================================================
// softmax over T per batch; writes attention_weights + coverage
// ============================================================================
__global__ void softmax_kernel(const float* __restrict__ prev_cov,
                               const float* __restrict__ Vb,
                               float* __restrict__ out) {
    __shared__ float sc[T_];
    __shared__ float red[256];
    const int b = blockIdx.x;
    const int tid = threadIdx.x;
    const float vb = Vb[0];

    float lmax = -1e30f;
    for (int t = tid; t < T_; t += 256) {
        size_t i = (size_t)b * T_ + t;
        float s = g_spart[i] + g_spart[M_ + i] + g_spart[2 * (size_t)M_ + i]
                + g_spart[3 * (size_t)M_ + i] + vb;
        sc[t] = s;
        lmax = fmaxf(lmax, s);
    }
    red[tid] = lmax;
    __syncthreads();
    for (int st = 128; st > 0; st >>= 1) {
        if (tid < st) red[tid] = fmaxf(red[tid], red[tid + st]);
        __syncthreads();
    }
    const float mx = red[0];
    __syncthreads();

    float lsum = 0.0f;
    for (int t = tid; t < T_; t += 256) {
        float e = expf(sc[t] - mx);
        sc[t] = e;
        lsum += e;
    }
    red[tid] = lsum;
    __syncthreads();
    for (int st = 128; st > 0; st >>= 1) {
        if (tid < st) red[tid] += red[tid + st];
        __syncthreads();
    }
    const float inv = 1.0f / red[0];

    float* aw_out  = out + B_ * D_;
    float* cov_out = out + B_ * D_ + B_ * T_;
    const float* pc = prev_cov + (size_t)b * T_;
    for (int t = tid; t < T_; t += 256) {
        float a = sc[t] * inv;
        aw_out[(size_t)b * T_ + t]  = a;
        cov_out[(size_t)b * T_ + t] = a + pc[t];
    }
}

// ============================================================================
// context partials from fp16 g_va (de-swizzled reads): grid (16 tc, 32 b),
// 256 threads = 128 d-units x 2 t-parity halves; + reduce
// ============================================================================
__global__ void ctx_part_kernel(const float* __restrict__ aw_src) {
    const int tc = blockIdx.x, b = blockIdx.y, tid = threadIdx.x;
    __shared__ float sa[128];
    const int t0 = tc * 128;
    if (tid < 128) sa[tid] = aw_src[(size_t)b * T_ + t0 + tid];
    __syncthreads();

    const int j   = tid & 127;           // d-unit: d = j*8 .. j*8+7
    const int par = tid >> 7;            // t parity
    const int c   = j >> 2;              // chunk
    const int u   = j & 3;               // 16B unit within 64B block
    const size_t mbase = (size_t)b * T_ + t0;

    float acc[8];
    #pragma unroll
    for (int e = 0; e < 8; ++e) acc[e] = 0.f;

    #pragma unroll 4
    for (int i = 0; i < 64; ++i) {
        int tl = 2 * i + par;
        size_t m = mbase + tl;
        int sw = (u ^ (((int)m >> 1) & 3)) & 3;
        uint4 raw = *(const uint4*)(g_va + ((size_t)c * M_ + m) * 32 + sw * 8);
        const __half2* hp = (const __half2*)&raw;
        float a = sa[tl];
        #pragma unroll
        for (int q = 0; q < 4; ++q) {
            float2 f = __half22float2(hp[q]);
            acc[2 * q]     = fmaf(a, f.x, acc[2 * q]);
            acc[2 * q + 1] = fmaf(a, f.y, acc[2 * q + 1]);
        }
    }
    float* dst = g_ctxpart + ((size_t)(tc * 2 + par) * B_ + b) * D_ + j * 8;
    #pragma unroll
    for (int e = 0; e < 8; ++e) dst[e] = acc[e];
}

__global__ void ctx_reduce_kernel(float* __restrict__ out) {
    int g = blockIdx.x * blockDim.x + threadIdx.x;
    float s = 0.0f;
    #pragma unroll
    for (int tc = 0; tc < NCTXP; ++tc)
        s += g_ctxpart[(size_t)tc * B_ * D_ + g];
    out[g] = s;
}

// ============================================================================
extern "C" void kernel_launch(void* const* d_in, const int* in_sizes, int n_in,
                              void* d_out, int out_size) {
    const float* query    = (const float*)d_in[0];
    const float* values   = (const float*)d_in[1];
    const float* prev_cov = (const float*)d_in[2];
    const float* Wh       = (const float*)d_in[3];
    const float* bh       = (const float*)d_in[4];
    const float* Ws       = (const float*)d_in[5];
    const float* bs       = (const float*)d_in[6];
    const float* Wc       = (const float*)d_in[7];
    const float* bc       = (const float*)d_in[8];
    const float* Vw       = (const float*)d_in[9];
    const float* Vb       = (const float*)d_in[10];
    float* out = (float*)d_out;

    cudaFuncSetAttribute(score_gemm_kernel,
                         cudaFuncAttributeMaxDynamicSharedMemorySize, GEMM_SMEM);

    prep_kernel<<<NB_CV + NB_CW + NB_QP, 256>>>(values, Ws, query, Wh, bh, bs, bc);
    score_gemm_kernel<<<dim3(4, M_ / 128), 256, GEMM_SMEM>>>(prev_cov, Wc, Vw);
    softmax_kernel<<<B_, 256>>>(prev_cov, Vb, out);
    ctx_part_kernel<<<dim3(16, B_), 256>>>(out + B_ * D_);
    ctx_reduce_kernel<<<(B_ * D_) / 256, 256>>>(out);
}